// round 1
// baseline (speedup 1.0000x reference)
#include <cuda_runtime.h>
#include <cmath>

#define NN   50000
#define NE   800000
#define HD   128
#define FFD  256
#define NL   6

// ---------------- scratch (static device globals; no allocs allowed) --------
__device__ float g_z[NN*HD];
__device__ float g_q[NN*HD];
__device__ float g_k[NN*HD];
__device__ float g_v[NN*HD];
__device__ float g_sk[NN*HD];
__device__ float g_msg[NN*HD];
__device__ float g_h[NN*HD];
__device__ float g_t[NN*HD];
__device__ float g_ff[NN*FFD];
__device__ float g_score[NE*2];
__device__ float g_smax[NN*2];
__device__ float g_denom[NN*2];
__device__ float g_betas[NL+1];
__device__ int   g_mode;        // 1 = edge_index is int64, 0 = int32

// ---------------- helpers ---------------------------------------------------
__device__ __forceinline__ float warp_sum(float v){
#pragma unroll
    for (int o = 16; o; o >>= 1) v += __shfl_xor_sync(0xffffffffu, v, o);
    return v;
}

__device__ __forceinline__ void atomicMaxF(float* addr, float val){
    if (val >= 0.f) atomicMax((int*)addr, __float_as_int(val));
    else            atomicMin((unsigned int*)addr, __float_as_uint(val));
}

__device__ __forceinline__ void load_edge(const void* ei, int e, long long& s, long long& d){
    if (g_mode){ const long long* p = (const long long*)ei; s = p[e]; d = p[NE + e]; }
    else       { const int*       p = (const int*)ei;       s = p[e]; d = p[NE + e]; }
}

// Detect int64 vs int32 edge_index: for int64 (values < 2^31), every odd
// 32-bit word is zero. For int32 random indices that is astronomically unlikely.
__global__ void detect_kernel(const int* w){
    __shared__ int any;
    if (threadIdx.x == 0) any = 0;
    __syncthreads();
    int loc = 0;
    for (int i = threadIdx.x; i < 2048; i += blockDim.x) loc |= w[2*i + 1];
    if (loc) atomicOr(&any, 1);
    __syncthreads();
    if (threadIdx.x == 0) g_mode = any ? 0 : 1;
}

__global__ void betas_kernel(const float* __restrict__ beta){
    if (threadIdx.x == 0 && blockIdx.x == 0){
        float m = -INFINITY;
        for (int i = 0; i < NL+1; i++) m = fmaxf(m, beta[i]);
        float e[NL+1], s = 0.f;
        for (int i = 0; i < NL+1; i++){ e[i] = expf(beta[i] - m); s += e[i]; }
        for (int i = 0; i < NL+1; i++) g_betas[i] = e[i] / s;
    }
}

// ---------------- SGEMM: C[M,Ncol] = act(A[M,K] @ B[K,Ncol] + bias) ---------
// BM=BN=128, BK=8, 256 threads, 8x8 register tile per thread.
template<int ACT>
__global__ __launch_bounds__(256) void sgemm(
    int M, int K, int Ncol,
    const float* __restrict__ A, const float* __restrict__ B,
    const float* __restrict__ bias, float* __restrict__ C)
{
    __shared__ __align__(16) float As[8][132];   // +4 pad: conflict-free stores, 16B-aligned rows
    __shared__ __align__(16) float Bs[8][128];

    const int tid = threadIdx.x;
    const int tx = tid & 15, ty = tid >> 4;
    const int rowBase = blockIdx.y * 128, colBase = blockIdx.x * 128;
    const int aRow = tid >> 1, aCol = (tid & 1) * 4;
    const int bRow = tid >> 5, bCol = (tid & 31) * 4;

    float acc[8][8];
#pragma unroll
    for (int i = 0; i < 8; i++)
#pragma unroll
        for (int j = 0; j < 8; j++) acc[i][j] = 0.f;

    for (int k0 = 0; k0 < K; k0 += 8){
        float4 av = make_float4(0.f, 0.f, 0.f, 0.f);
        int ar = rowBase + aRow;
        if (ar < M) av = *(const float4*)(A + (size_t)ar*K + k0 + aCol);
        As[aCol+0][aRow] = av.x; As[aCol+1][aRow] = av.y;
        As[aCol+2][aRow] = av.z; As[aCol+3][aRow] = av.w;
        *(float4*)&Bs[bRow][bCol] =
            *(const float4*)(B + (size_t)(k0 + bRow)*Ncol + colBase + bCol);
        __syncthreads();
#pragma unroll
        for (int k = 0; k < 8; k++){
            float4 a0 = *(const float4*)&As[k][ty*8];
            float4 a1 = *(const float4*)&As[k][ty*8 + 4];
            float4 b0 = *(const float4*)&Bs[k][tx*8];
            float4 b1 = *(const float4*)&Bs[k][tx*8 + 4];
            float am[8] = {a0.x,a0.y,a0.z,a0.w,a1.x,a1.y,a1.z,a1.w};
            float bn[8] = {b0.x,b0.y,b0.z,b0.w,b1.x,b1.y,b1.z,b1.w};
#pragma unroll
            for (int i = 0; i < 8; i++)
#pragma unroll
                for (int j = 0; j < 8; j++)
                    acc[i][j] = fmaf(am[i], bn[j], acc[i][j]);
        }
        __syncthreads();
    }

#pragma unroll
    for (int i = 0; i < 8; i++){
        int r = rowBase + ty*8 + i;
        if (r >= M) break;
#pragma unroll
        for (int j = 0; j < 8; j++){
            int c = colBase + tx*8 + j;
            float v = acc[i][j] + bias[c];
            if (ACT == 1)      v = fmaxf(v, 0.f);
            else if (ACT == 2) v = 0.5f * v * (1.f + erff(v * 0.70710678118654752f));
            C[(size_t)r*Ncol + c] = v;
        }
    }
}

// ---------------- edge phase ------------------------------------------------
__global__ void init_edge_kernel(){
    int i = blockIdx.x * blockDim.x + threadIdx.x;
    if (i < NN*HD) g_msg[i] = 0.f;
    if (i < NN*2){ g_denom[i] = 0.f; g_smax[i] = -INFINITY; }
}

// one warp per edge: score[e,h] = (q[dst]·k[src])_h / 8 ; segment max into smax
__global__ void score_kernel(const void* __restrict__ ei){
    int gw   = (blockIdx.x * blockDim.x + threadIdx.x) >> 5;
    int lane = threadIdx.x & 31;
    if (gw >= NE) return;
    long long s, d; load_edge(ei, gw, s, d);
    float4 qv = *(const float4*)(g_q + (size_t)d*HD + lane*4);
    float4 kv = *(const float4*)(g_k + (size_t)s*HD + lane*4);
    float dot = qv.x*kv.x + qv.y*kv.y + qv.z*kv.z + qv.w*kv.w;
#pragma unroll
    for (int o = 8; o; o >>= 1) dot += __shfl_xor_sync(0xffffffffu, dot, o);
    float sc = dot * 0.125f;                     // / sqrt(64)
    if (lane == 0 ){ g_score[2*(size_t)gw  ] = sc; atomicMaxF(&g_smax[d*2  ], sc); }
    if (lane == 16){ g_score[2*(size_t)gw+1] = sc; atomicMaxF(&g_smax[d*2+1], sc); }
}

// one warp per edge: w = exp(score - smax[dst]); denom += w; msg[dst] += w*v[src]
__global__ void accum_kernel(const void* __restrict__ ei){
    int gw   = (blockIdx.x * blockDim.x + threadIdx.x) >> 5;
    int lane = threadIdx.x & 31;
    if (gw >= NE) return;
    long long s, d; load_edge(ei, gw, s, d);
    int h = lane >> 4;
    float sc = g_score[2*(size_t)gw + h];
    float m  = g_smax[d*2 + h];
    float w  = expf(sc - m);
    if (lane == 0 ) atomicAdd(&g_denom[d*2  ], w);
    if (lane == 16) atomicAdd(&g_denom[d*2+1], w);
    float4 vv = *(const float4*)(g_v + (size_t)s*HD + lane*4);
    float* mp = g_msg + (size_t)d*HD + lane*4;
    atomicAdd(mp+0, w*vv.x);
    atomicAdd(mp+1, w*vv.y);
    atomicAdd(mp+2, w*vv.z);
    atomicAdd(mp+3, w*vv.w);
}

// ---------------- layernorms (one warp per node) ----------------------------
// h = LN(z + msg/denom + sk) * g + b
__global__ void ln1_kernel(const float* __restrict__ g, const float* __restrict__ b){
    int node = (blockIdx.x * blockDim.x + threadIdx.x) >> 5;
    int lane = threadIdx.x & 31;
    if (node >= NN) return;
    float den = g_denom[node*2 + (lane >> 4)];
    float inv = den > 0.f ? 1.f/den : 0.f;
    size_t base = (size_t)node*HD + lane*4;
    float4 zv = *(const float4*)(g_z   + base);
    float4 mv = *(const float4*)(g_msg + base);
    float4 sv = *(const float4*)(g_sk  + base);
    float u[4] = { zv.x + mv.x*inv + sv.x, zv.y + mv.y*inv + sv.y,
                   zv.z + mv.z*inv + sv.z, zv.w + mv.w*inv + sv.w };
    float mu = warp_sum(u[0]+u[1]+u[2]+u[3]) * (1.f/HD);
    float vr = 0.f;
#pragma unroll
    for (int i = 0; i < 4; i++){ float dl = u[i]-mu; vr += dl*dl; }
    vr = warp_sum(vr) * (1.f/HD);
    float rs = rsqrtf(vr + 1e-5f);
    float4 gv = *(const float4*)(g + lane*4);
    float4 bv = *(const float4*)(b + lane*4);
    float4 o;
    o.x = (u[0]-mu)*rs*gv.x + bv.x;
    o.y = (u[1]-mu)*rs*gv.y + bv.y;
    o.z = (u[2]-mu)*rs*gv.z + bv.z;
    o.w = (u[3]-mu)*rs*gv.w + bv.w;
    *(float4*)(g_h + base) = o;
}

// z = relu(LN(h + t)); out += betas[idx] * z
__global__ void ln2_kernel(const float* __restrict__ g, const float* __restrict__ b,
                           int betaIdx, float* __restrict__ out){
    int node = (blockIdx.x * blockDim.x + threadIdx.x) >> 5;
    int lane = threadIdx.x & 31;
    if (node >= NN) return;
    size_t base = (size_t)node*HD + lane*4;
    float4 hv = *(const float4*)(g_h + base);
    float4 tv = *(const float4*)(g_t + base);
    float u[4] = { hv.x+tv.x, hv.y+tv.y, hv.z+tv.z, hv.w+tv.w };
    float mu = warp_sum(u[0]+u[1]+u[2]+u[3]) * (1.f/HD);
    float vr = 0.f;
#pragma unroll
    for (int i = 0; i < 4; i++){ float dl = u[i]-mu; vr += dl*dl; }
    vr = warp_sum(vr) * (1.f/HD);
    float rs = rsqrtf(vr + 1e-5f);
    float4 gv = *(const float4*)(g + lane*4);
    float4 bv = *(const float4*)(b + lane*4);
    float zz[4];
#pragma unroll
    for (int i = 0; i < 4; i++){
        float y = (u[i]-mu)*rs;
        y = y * ((i==0)?gv.x:(i==1)?gv.y:(i==2)?gv.z:gv.w)
              + ((i==0)?bv.x:(i==1)?bv.y:(i==2)?bv.z:bv.w);
        zz[i] = fmaxf(y, 0.f);
    }
    *(float4*)(g_z + base) = make_float4(zz[0], zz[1], zz[2], zz[3]);
    float bb = g_betas[betaIdx];
    float4 o = *(float4*)(out + base);
    o.x += bb*zz[0]; o.y += bb*zz[1]; o.z += bb*zz[2]; o.w += bb*zz[3];
    *(float4*)(out + base) = o;
}

__global__ void acc_init_kernel(float* __restrict__ out){
    int i = blockIdx.x * blockDim.x + threadIdx.x;
    if (i < NN*HD) out[i] = g_betas[0] * g_z[i];
}

// ---------------- driver ----------------------------------------------------
extern "C" void kernel_launch(void* const* d_in, const int* in_sizes, int n_in,
                              void* d_out, int out_size)
{
    const float* x    = (const float*)d_in[0];
    const void*  ei   = d_in[1];
    const float* Win  = (const float*)d_in[2];
    const float* b_in = (const float*)d_in[3];
    const float* Wq   = (const float*)d_in[4];
    const float* bq   = (const float*)d_in[5];
    const float* Wk   = (const float*)d_in[6];
    const float* bk   = (const float*)d_in[7];
    const float* Wv   = (const float*)d_in[8];
    const float* bv   = (const float*)d_in[9];
    const float* Wsk  = (const float*)d_in[10];
    const float* bsk  = (const float*)d_in[11];
    const float* W1   = (const float*)d_in[12];
    const float* b1   = (const float*)d_in[13];
    const float* W2   = (const float*)d_in[14];
    const float* b2   = (const float*)d_in[15];
    const float* g1   = (const float*)d_in[16];
    const float* bt1  = (const float*)d_in[17];
    const float* g2   = (const float*)d_in[18];
    const float* bt2  = (const float*)d_in[19];
    const float* beta = (const float*)d_in[20];
    float* out = (float*)d_out;

    float *zP, *qP, *kP, *vP, *skP, *hP, *tP, *ffP;
    cudaGetSymbolAddress((void**)&zP,  g_z);
    cudaGetSymbolAddress((void**)&qP,  g_q);
    cudaGetSymbolAddress((void**)&kP,  g_k);
    cudaGetSymbolAddress((void**)&vP,  g_v);
    cudaGetSymbolAddress((void**)&skP, g_sk);
    cudaGetSymbolAddress((void**)&hP,  g_h);
    cudaGetSymbolAddress((void**)&tP,  g_t);
    cudaGetSymbolAddress((void**)&ffP, g_ff);

    detect_kernel<<<1, 256>>>((const int*)ei);
    betas_kernel<<<1, 32>>>(beta);

    dim3 g128(1, (NN + 127) / 128);
    dim3 g256(2, (NN + 127) / 128);
    const int EB  = (NE * 32 + 255) / 256;   // edge kernels, warp/edge
    const int LNB = (NN + 7) / 8;            // ln kernels, warp/node
    const int IB  = (NN * HD + 255) / 256;

    // z = relu(x @ Win + b_in); acc = betas[0] * z
    sgemm<1><<<g128, 256>>>(NN, HD, HD, x, Win, b_in, zP);
    acc_init_kernel<<<IB, 256>>>(out);

    for (int l = 0; l < NL; l++){
        const float* Wql  = Wq  + (size_t)l*HD*HD;
        const float* Wkl  = Wk  + (size_t)l*HD*HD;
        const float* Wvl  = Wv  + (size_t)l*HD*HD;
        const float* Wskl = Wsk + (size_t)l*HD*HD;
        sgemm<0><<<g128, 256>>>(NN, HD, HD, zP, Wql,  bq  + l*HD, qP);
        sgemm<0><<<g128, 256>>>(NN, HD, HD, zP, Wkl,  bk  + l*HD, kP);
        sgemm<0><<<g128, 256>>>(NN, HD, HD, zP, Wvl,  bv  + l*HD, vP);
        sgemm<0><<<g128, 256>>>(NN, HD, HD, zP, Wskl, bsk + l*HD, skP);

        init_edge_kernel<<<IB, 256>>>();
        score_kernel<<<EB, 256>>>(ei);
        accum_kernel<<<EB, 256>>>(ei);

        ln1_kernel<<<LNB, 256>>>(g1 + l*HD, bt1 + l*HD);

        sgemm<2><<<g256, 256>>>(NN, HD,  FFD, hP,  W1 + (size_t)l*HD*FFD, b1 + l*FFD, ffP);
        sgemm<0><<<g128, 256>>>(NN, FFD, HD,  ffP, W2 + (size_t)l*FFD*HD, b2 + l*HD,  tP);

        ln2_kernel<<<LNB, 256>>>(g2 + l*HD, bt2 + l*HD, l + 1, out);
    }
}

// round 7
// speedup vs baseline: 1.5011x; 1.5011x over previous
#include <cuda_runtime.h>
#include <cmath>
#include <cstdint>

#define NN   50000
#define NE   800000
#define HD   128
#define FFD  256
#define NL   6

// ---------------- scratch (static device globals; no allocs allowed) --------
__device__ float g_z[NN*HD];
__device__ float g_q[NN*HD];
__device__ float g_k[NN*HD];
__device__ float g_v[NN*HD];
__device__ float g_sk[NN*HD];
__device__ float g_msg[NN*HD];
__device__ float g_h[NN*HD];
__device__ float g_t[NN*HD];
__device__ float g_ff[NN*FFD];
__device__ float g_wt[512*128];       // transposed weight staging [Ntot][K]
__device__ float g_score[NE*2];
__device__ float g_smax[NN*2];
__device__ float g_denom[NN*2];
__device__ float g_betas[NL+1];
__device__ int   g_mode;              // 1 = edge_index is int64, 0 = int32

// ---------------- helpers ---------------------------------------------------
__device__ __forceinline__ float warp_sum(float v){
#pragma unroll
    for (int o = 16; o; o >>= 1) v += __shfl_xor_sync(0xffffffffu, v, o);
    return v;
}
__device__ __forceinline__ void atomicMaxF(float* addr, float val){
    if (val >= 0.f) atomicMax((int*)addr, __float_as_int(val));
    else            atomicMin((unsigned int*)addr, __float_as_uint(val));
}
__device__ __forceinline__ void load_edge(const void* ei, int e, long long& s, long long& d){
    if (g_mode){ const long long* p = (const long long*)ei; s = p[e]; d = p[NE + e]; }
    else       { const int*       p = (const int*)ei;       s = p[e]; d = p[NE + e]; }
}
__device__ __forceinline__ uint32_t to_tf32(float v){
    uint32_t r; asm("cvt.rna.tf32.f32 %0, %1;" : "=r"(r) : "f"(v)); return r;
}
// D += A(16x8) * B(8x8), tf32 inputs, f32 accum
__device__ __forceinline__ void mma_tf32(float* c, const uint32_t* a, const uint32_t* b){
    asm volatile(
        "mma.sync.aligned.m16n8k8.row.col.f32.tf32.tf32.f32 "
        "{%0,%1,%2,%3}, {%4,%5,%6,%7}, {%8,%9}, {%0,%1,%2,%3};"
        : "+f"(c[0]), "+f"(c[1]), "+f"(c[2]), "+f"(c[3])
        : "r"(a[0]), "r"(a[1]), "r"(a[2]), "r"(a[3]), "r"(b[0]), "r"(b[1]));
}

__global__ void detect_kernel(const int* w){
    __shared__ int any;
    if (threadIdx.x == 0) any = 0;
    __syncthreads();
    int loc = 0;
    for (int i = threadIdx.x; i < 2048; i += blockDim.x) loc |= w[2*i + 1];
    if (loc) atomicOr(&any, 1);
    __syncthreads();
    if (threadIdx.x == 0) g_mode = any ? 0 : 1;
}

__global__ void betas_kernel(const float* __restrict__ beta){
    if (threadIdx.x == 0 && blockIdx.x == 0){
        float m = -INFINITY;
        for (int i = 0; i < NL+1; i++) m = fmaxf(m, beta[i]);
        float e[NL+1], s = 0.f;
        for (int i = 0; i < NL+1; i++){ e[i] = expf(beta[i] - m); s += e[i]; }
        for (int i = 0; i < NL+1; i++) g_betas[i] = e[i] / s;
    }
}

// ---------------- weight transposes ------------------------------------------
// 4 x [128,128] (k-major [k][n]) -> g_wt[j*16384 + n*128 + k]
__global__ void transpose4_kernel(const float* __restrict__ W0, const float* __restrict__ W1,
                                  const float* __restrict__ W2, const float* __restrict__ W3){
    int i = blockIdx.x * blockDim.x + threadIdx.x;
    if (i >= 4*128*128) return;
    int j = i >> 14, r = i & 16383, n = r >> 7, k = r & 127;
    const float* W = (j==0)?W0:(j==1)?W1:(j==2)?W2:W3;
    g_wt[(j<<14) + n*128 + k] = W[k*128 + n];
}
// generic: W [K,N] row-major -> dst [N,K]
__global__ void transpose_kernel(const float* __restrict__ W, int K, int N, float* __restrict__ dst){
    int i = blockIdx.x * blockDim.x + threadIdx.x;
    if (i >= K*N) return;
    int n = i / K, k = i - n*K;
    dst[i] = W[k*N + n];
}

// ---------------- tf32 mma.sync GEMM -----------------------------------------
// C_tile[xt] = act(A[M,K] @ Bt[xt][128,K]^T + bias[xt]).  CTA tile 128x128.
// 8 warps: 2 (M) x 4 (N); warp tile 64x32; BK=16.
struct GemmOuts { float* o[4]; const float* b[4]; };

template<int ACT>
__global__ __launch_bounds__(256) void gemm_mma(
    int M, int K, const float* __restrict__ A, const float* __restrict__ Bt,
    GemmOuts outs, int ldc)
{
    __shared__ float As[16][136];   // [k][m], tf32-rounded; (k*8+m)%32 conflict-free
    __shared__ float Bs[16][136];   // [k][n]

    const int tid = threadIdx.x, wid = tid >> 5, lane = tid & 31;
    const int gid = lane >> 2, tig = lane & 3;
    const int mbase = blockIdx.y * 128;
    const int xt = blockIdx.x;
    const int wm = (wid & 1) * 64, wn = (wid >> 1) * 32;

    float c[4][4][4];
#pragma unroll
    for (int i = 0; i < 4; i++)
#pragma unroll
        for (int j = 0; j < 4; j++){
            c[i][j][0] = 0.f; c[i][j][1] = 0.f; c[i][j][2] = 0.f; c[i][j][3] = 0.f;
        }

    const float* Bsrc = Bt + (size_t)xt * 128 * K;
    const int mld = tid & 127, hld = tid >> 7;      // hld in {0,1}
    const bool arow_ok = (mbase + mld) < M;

    for (int k0 = 0; k0 < K; k0 += 16){
        const float* Ap = A + (size_t)(mbase + mld) * K + k0 + hld*8;
        const float* Bp = Bsrc + (size_t)mld * K + k0 + hld*8;
        float4 av0 = arow_ok ? __ldg((const float4*)Ap)       : make_float4(0,0,0,0);
        float4 av1 = arow_ok ? __ldg((const float4*)(Ap + 4)) : make_float4(0,0,0,0);
        float4 bv0 = __ldg((const float4*)Bp);
        float4 bv1 = __ldg((const float4*)(Bp + 4));
        const int kb = hld * 8;
        As[kb+0][mld] = __uint_as_float(to_tf32(av0.x));
        As[kb+1][mld] = __uint_as_float(to_tf32(av0.y));
        As[kb+2][mld] = __uint_as_float(to_tf32(av0.z));
        As[kb+3][mld] = __uint_as_float(to_tf32(av0.w));
        As[kb+4][mld] = __uint_as_float(to_tf32(av1.x));
        As[kb+5][mld] = __uint_as_float(to_tf32(av1.y));
        As[kb+6][mld] = __uint_as_float(to_tf32(av1.z));
        As[kb+7][mld] = __uint_as_float(to_tf32(av1.w));
        Bs[kb+0][mld] = __uint_as_float(to_tf32(bv0.x));
        Bs[kb+1][mld] = __uint_as_float(to_tf32(bv0.y));
        Bs[kb+2][mld] = __uint_as_float(to_tf32(bv0.z));
        Bs[kb+3][mld] = __uint_as_float(to_tf32(bv0.w));
        Bs[kb+4][mld] = __uint_as_float(to_tf32(bv1.x));
        Bs[kb+5][mld] = __uint_as_float(to_tf32(bv1.y));
        Bs[kb+6][mld] = __uint_as_float(to_tf32(bv1.z));
        Bs[kb+7][mld] = __uint_as_float(to_tf32(bv1.w));
        __syncthreads();

#pragma unroll
        for (int kk = 0; kk < 16; kk += 8){
            uint32_t a[4][4], b[4][2];
#pragma unroll
            for (int mf = 0; mf < 4; mf++){
                int m = wm + mf*16 + gid;
                a[mf][0] = __float_as_uint(As[kk+tig  ][m]);
                a[mf][1] = __float_as_uint(As[kk+tig  ][m+8]);
                a[mf][2] = __float_as_uint(As[kk+tig+4][m]);
                a[mf][3] = __float_as_uint(As[kk+tig+4][m+8]);
            }
#pragma unroll
            for (int nf = 0; nf < 4; nf++){
                int n = wn + nf*8 + gid;
                b[nf][0] = __float_as_uint(Bs[kk+tig  ][n]);
                b[nf][1] = __float_as_uint(Bs[kk+tig+4][n]);
            }
#pragma unroll
            for (int mf = 0; mf < 4; mf++)
#pragma unroll
                for (int nf = 0; nf < 4; nf++)
                    mma_tf32(c[mf][nf], a[mf], b[nf]);
        }
        __syncthreads();
    }

    // epilogue: c0:(m,n) c1:(m,n+1) c2:(m+8,n) c3:(m+8,n+1); n = wn+nf*8+tig*2
    float* obase = outs.o[xt];
    const float* bb = outs.b[xt];
#pragma unroll
    for (int mf = 0; mf < 4; mf++){
#pragma unroll
        for (int half = 0; half < 2; half++){
            int m = mbase + wm + mf*16 + gid + half*8;
            if (m >= M) continue;
            float* op = obase + (size_t)m * ldc;
#pragma unroll
            for (int nf = 0; nf < 4; nf++){
                int n = wn + nf*8 + tig*2;
                float v0 = c[mf][nf][half*2+0] + __ldg(bb + n);
                float v1 = c[mf][nf][half*2+1] + __ldg(bb + n + 1);
                if (ACT == 1){
                    v0 = fmaxf(v0, 0.f); v1 = fmaxf(v1, 0.f);
                } else if (ACT == 2){
                    const float is2 = 0.70710678118654752f;
                    v0 = 0.5f*v0*(1.f + erff(v0*is2));
                    v1 = 0.5f*v1*(1.f + erff(v1*is2));
                }
                *(float2*)(op + n) = make_float2(v0, v1);
            }
        }
    }
}

// ---------------- edge phase -------------------------------------------------
__global__ void init_edge_kernel(){
    int i = blockIdx.x * blockDim.x + threadIdx.x;
    if (i < NN*HD) g_msg[i] = 0.f;
    if (i < NN*2){ g_denom[i] = 0.f; g_smax[i] = -INFINITY; }
}

__global__ void score_kernel(const void* __restrict__ ei){
    int gw   = (blockIdx.x * blockDim.x + threadIdx.x) >> 5;
    int lane = threadIdx.x & 31;
    if (gw >= NE) return;
    long long s, d; load_edge(ei, gw, s, d);
    float4 qv = *(const float4*)(g_q + (size_t)d*HD + lane*4);
    float4 kv = *(const float4*)(g_k + (size_t)s*HD + lane*4);
    float dot = qv.x*kv.x + qv.y*kv.y + qv.z*kv.z + qv.w*kv.w;
#pragma unroll
    for (int o = 8; o; o >>= 1) dot += __shfl_xor_sync(0xffffffffu, dot, o);
    float sc = dot * 0.125f;
    if (lane == 0 ){ g_score[2*(size_t)gw  ] = sc; atomicMaxF(&g_smax[d*2  ], sc); }
    if (lane == 16){ g_score[2*(size_t)gw+1] = sc; atomicMaxF(&g_smax[d*2+1], sc); }
}

__global__ void accum_kernel(const void* __restrict__ ei){
    int gw   = (blockIdx.x * blockDim.x + threadIdx.x) >> 5;
    int lane = threadIdx.x & 31;
    if (gw >= NE) return;
    long long s, d; load_edge(ei, gw, s, d);
    int h = lane >> 4;
    float sc = g_score[2*(size_t)gw + h];
    float m  = g_smax[d*2 + h];
    float w  = expf(sc - m);
    if (lane == 0 ) atomicAdd(&g_denom[d*2  ], w);
    if (lane == 16) atomicAdd(&g_denom[d*2+1], w);
    float4 vv = *(const float4*)(g_v + (size_t)s*HD + lane*4);
    float* mp = g_msg + (size_t)d*HD + lane*4;
    atomicAdd(mp+0, w*vv.x);
    atomicAdd(mp+1, w*vv.y);
    atomicAdd(mp+2, w*vv.z);
    atomicAdd(mp+3, w*vv.w);
}

// ---------------- layernorms -------------------------------------------------
__global__ void ln1_kernel(const float* __restrict__ g, const float* __restrict__ b){
    int node = (blockIdx.x * blockDim.x + threadIdx.x) >> 5;
    int lane = threadIdx.x & 31;
    if (node >= NN) return;
    float den = g_denom[node*2 + (lane >> 4)];
    float inv = den > 0.f ? 1.f/den : 0.f;
    size_t base = (size_t)node*HD + lane*4;
    float4 zv = *(const float4*)(g_z   + base);
    float4 mv = *(const float4*)(g_msg + base);
    float4 sv = *(const float4*)(g_sk  + base);
    float u[4] = { zv.x + mv.x*inv + sv.x, zv.y + mv.y*inv + sv.y,
                   zv.z + mv.z*inv + sv.z, zv.w + mv.w*inv + sv.w };
    float mu = warp_sum(u[0]+u[1]+u[2]+u[3]) * (1.f/HD);
    float vr = 0.f;
#pragma unroll
    for (int i = 0; i < 4; i++){ float dl = u[i]-mu; vr += dl*dl; }
    vr = warp_sum(vr) * (1.f/HD);
    float rs = rsqrtf(vr + 1e-5f);
    float4 gv = *(const float4*)(g + lane*4);
    float4 bv = *(const float4*)(b + lane*4);
    float4 o;
    o.x = (u[0]-mu)*rs*gv.x + bv.x;
    o.y = (u[1]-mu)*rs*gv.y + bv.y;
    o.z = (u[2]-mu)*rs*gv.z + bv.z;
    o.w = (u[3]-mu)*rs*gv.w + bv.w;
    *(float4*)(g_h + base) = o;
}

__global__ void ln2_kernel(const float* __restrict__ g, const float* __restrict__ b,
                           int betaIdx, float* __restrict__ out){
    int node = (blockIdx.x * blockDim.x + threadIdx.x) >> 5;
    int lane = threadIdx.x & 31;
    if (node >= NN) return;
    size_t base = (size_t)node*HD + lane*4;
    float4 hv = *(const float4*)(g_h + base);
    float4 tv = *(const float4*)(g_t + base);
    float u[4] = { hv.x+tv.x, hv.y+tv.y, hv.z+tv.z, hv.w+tv.w };
    float mu = warp_sum(u[0]+u[1]+u[2]+u[3]) * (1.f/HD);
    float vr = 0.f;
#pragma unroll
    for (int i = 0; i < 4; i++){ float dl = u[i]-mu; vr += dl*dl; }
    vr = warp_sum(vr) * (1.f/HD);
    float rs = rsqrtf(vr + 1e-5f);
    float4 gv = *(const float4*)(g + lane*4);
    float4 bv = *(const float4*)(b + lane*4);
    float zz[4];
#pragma unroll
    for (int i = 0; i < 4; i++){
        float y = (u[i]-mu)*rs;
        y = y * ((i==0)?gv.x:(i==1)?gv.y:(i==2)?gv.z:gv.w)
              + ((i==0)?bv.x:(i==1)?bv.y:(i==2)?bv.z:bv.w);
        zz[i] = fmaxf(y, 0.f);
    }
    *(float4*)(g_z + base) = make_float4(zz[0], zz[1], zz[2], zz[3]);
    float bb = g_betas[betaIdx];
    float4 o = *(float4*)(out + base);
    o.x += bb*zz[0]; o.y += bb*zz[1]; o.z += bb*zz[2]; o.w += bb*zz[3];
    *(float4*)(out + base) = o;
}

__global__ void acc_init_kernel(float* __restrict__ out){
    int i = blockIdx.x * blockDim.x + threadIdx.x;
    if (i < NN*HD) out[i] = g_betas[0] * g_z[i];
}

// ---------------- driver -----------------------------------------------------
extern "C" void kernel_launch(void* const* d_in, const int* in_sizes, int n_in,
                              void* d_out, int out_size)
{
    const float* x    = (const float*)d_in[0];
    const void*  ei   = d_in[1];
    const float* Win  = (const float*)d_in[2];
    const float* b_in = (const float*)d_in[3];
    const float* Wq   = (const float*)d_in[4];
    const float* bq   = (const float*)d_in[5];
    const float* Wk   = (const float*)d_in[6];
    const float* bk   = (const float*)d_in[7];
    const float* Wv   = (const float*)d_in[8];
    const float* bv   = (const float*)d_in[9];
    const float* Wsk  = (const float*)d_in[10];
    const float* bsk  = (const float*)d_in[11];
    const float* W1   = (const float*)d_in[12];
    const float* b1   = (const float*)d_in[13];
    const float* W2   = (const float*)d_in[14];
    const float* b2   = (const float*)d_in[15];
    const float* g1   = (const float*)d_in[16];
    const float* bt1  = (const float*)d_in[17];
    const float* g2   = (const float*)d_in[18];
    const float* bt2  = (const float*)d_in[19];
    const float* beta = (const float*)d_in[20];
    float* out = (float*)d_out;

    float *zP, *qP, *kP, *vP, *skP, *hP, *tP, *ffP, *wtP;
    cudaGetSymbolAddress((void**)&zP,  g_z);
    cudaGetSymbolAddress((void**)&qP,  g_q);
    cudaGetSymbolAddress((void**)&kP,  g_k);
    cudaGetSymbolAddress((void**)&vP,  g_v);
    cudaGetSymbolAddress((void**)&skP, g_sk);
    cudaGetSymbolAddress((void**)&hP,  g_h);
    cudaGetSymbolAddress((void**)&tP,  g_t);
    cudaGetSymbolAddress((void**)&ffP, g_ff);
    cudaGetSymbolAddress((void**)&wtP, g_wt);

    detect_kernel<<<1, 256>>>((const int*)ei);
    betas_kernel<<<1, 32>>>(beta);

    const int MT  = (NN + 127) / 128;        // 391 M-tiles
    const int EB  = (NE * 32 + 255) / 256;   // edge kernels, warp/edge
    const int LNB = (NN + 7) / 8;            // ln kernels, warp/node
    const int IB  = (NN * HD + 255) / 256;

    // z = relu(x @ Win + b_in)
    transpose_kernel<<<(128*128 + 255)/256, 256>>>(Win, HD, HD, wtP);
    {
        GemmOuts o; o.o[0]=zP; o.b[0]=b_in;
        o.o[1]=o.o[2]=o.o[3]=zP; o.b[1]=o.b[2]=o.b[3]=b_in;
        gemm_mma<1><<<dim3(1, MT), 256>>>(NN, HD, x, wtP, o, HD);
    }
    acc_init_kernel<<<IB, 256>>>(out);

    for (int l = 0; l < NL; l++){
        // fused q/k/v/sk projections
        transpose4_kernel<<<(4*128*128 + 255)/256, 256>>>(
            Wq + (size_t)l*HD*HD, Wk + (size_t)l*HD*HD,
            Wv + (size_t)l*HD*HD, Wsk + (size_t)l*HD*HD);
        {
            GemmOuts o;
            o.o[0]=qP;  o.b[0]=bq  + l*HD;
            o.o[1]=kP;  o.b[1]=bk  + l*HD;
            o.o[2]=vP;  o.b[2]=bv  + l*HD;
            o.o[3]=skP; o.b[3]=bsk + l*HD;
            gemm_mma<0><<<dim3(4, MT), 256>>>(NN, HD, zP, wtP, o, HD);
        }

        init_edge_kernel<<<IB, 256>>>();
        score_kernel<<<EB, 256>>>(ei);
        accum_kernel<<<EB, 256>>>(ei);
        ln1_kernel<<<LNB, 256>>>(g1 + l*HD, bt1 + l*HD);

        // FFN: ff = gelu(h @ W1 + b1) ; t = ff @ W2 + b2
        transpose_kernel<<<(128*256 + 255)/256, 256>>>(W1 + (size_t)l*HD*FFD, HD, FFD, wtP);
        {
            GemmOuts o;
            o.o[0]=ffP;       o.b[0]=b1 + l*FFD;
            o.o[1]=ffP + 128; o.b[1]=b1 + l*FFD + 128;
            o.o[2]=o.o[3]=ffP; o.b[2]=o.b[3]=o.b[0];
            gemm_mma<2><<<dim3(2, MT), 256>>>(NN, HD, hP, wtP, o, FFD);
        }
        transpose_kernel<<<(256*128 + 255)/256, 256>>>(W2 + (size_t)l*FFD*HD, FFD, HD, wtP);
        {
            GemmOuts o; o.o[0]=tP; o.b[0]=b2 + l*HD;
            o.o[1]=o.o[2]=o.o[3]=tP; o.b[1]=o.b[2]=o.b[3]=o.b[0];
            gemm_mma<0><<<dim3(1, MT), 256>>>(NN, FFD, ffP, wtP, o, HD);
        }

        ln2_kernel<<<LNB, 256>>>(g2 + l*HD, bt2 + l*HD, l + 1, out);
    }
}

// round 10
// speedup vs baseline: 2.5792x; 1.7182x over previous
#include <cuda_runtime.h>
#include <cmath>
#include <cstdint>

#define NN   50000
#define NE   800000
#define HD   128
#define FFD  256
#define NL   6

// ---------------- scratch (static device globals; no allocs allowed) --------
__device__ float g_z[NN*HD];
__device__ float g_q[NN*HD];
__device__ float g_k[NN*HD];
__device__ float g_v[NN*HD];
__device__ float g_sk[NN*HD];
__device__ float g_msg[NN*HD];
__device__ float g_h[NN*HD];
__device__ float g_t[NN*HD];
__device__ float g_ff[NN*FFD];
__device__ float g_wt[512*128];       // transposed weight staging [Ntot][K]
__device__ float g_betas[NL+1];
__device__ int   g_mode;              // 1 = edge_index is int64, 0 = int32
// CSR
__device__ int g_cnt[NN];
__device__ int g_rowptr[NN];
__device__ int g_cursor[NN];
__device__ int g_esrc[NE];
__device__ int g_pscan[NN];
__device__ int g_bsum[128];
__device__ int g_boff[128];

// ---------------- helpers ---------------------------------------------------
__device__ __forceinline__ float warp_sum(float v){
#pragma unroll
    for (int o = 16; o; o >>= 1) v += __shfl_xor_sync(0xffffffffu, v, o);
    return v;
}
__device__ __forceinline__ void load_edge(const void* ei, int e, long long& s, long long& d){
    if (g_mode){ const long long* p = (const long long*)ei; s = p[e]; d = p[NE + e]; }
    else       { const int*       p = (const int*)ei;       s = p[e]; d = p[NE + e]; }
}
__device__ __forceinline__ uint32_t to_tf32(float v){
    uint32_t r; asm("cvt.rna.tf32.f32 %0, %1;" : "=r"(r) : "f"(v)); return r;
}
__device__ __forceinline__ void mma_tf32(float* c, const uint32_t* a, const uint32_t* b){
    asm volatile(
        "mma.sync.aligned.m16n8k8.row.col.f32.tf32.tf32.f32 "
        "{%0,%1,%2,%3}, {%4,%5,%6,%7}, {%8,%9}, {%0,%1,%2,%3};"
        : "+f"(c[0]), "+f"(c[1]), "+f"(c[2]), "+f"(c[3])
        : "r"(a[0]), "r"(a[1]), "r"(a[2]), "r"(a[3]), "r"(b[0]), "r"(b[1]));
}

__global__ void detect_kernel(const int* w){
    __shared__ int any;
    if (threadIdx.x == 0) any = 0;
    __syncthreads();
    int loc = 0;
    for (int i = threadIdx.x; i < 2048; i += blockDim.x) loc |= w[2*i + 1];
    if (loc) atomicOr(&any, 1);
    __syncthreads();
    if (threadIdx.x == 0) g_mode = any ? 0 : 1;
}

__global__ void betas_kernel(const float* __restrict__ beta){
    if (threadIdx.x == 0 && blockIdx.x == 0){
        float m = -INFINITY;
        for (int i = 0; i < NL+1; i++) m = fmaxf(m, beta[i]);
        float e[NL+1], s = 0.f;
        for (int i = 0; i < NL+1; i++){ e[i] = expf(beta[i] - m); s += e[i]; }
        for (int i = 0; i < NL+1; i++) g_betas[i] = e[i] / s;
    }
}

// ---------------- CSR build --------------------------------------------------
__global__ void csr_zero(){
    int i = blockIdx.x * blockDim.x + threadIdx.x;
    if (i < NN){ g_cnt[i] = 0; g_cursor[i] = 0; }
}
__global__ void csr_hist(const void* __restrict__ ei){
    int e = blockIdx.x * blockDim.x + threadIdx.x;
    if (e >= NE) return;
    long long s, d; load_edge(ei, e, s, d);
    atomicAdd(&g_cnt[(int)d], 1);
}
__global__ void csr_scanA(){
    __shared__ int sh[512];
    int b = blockIdx.x, t = threadIdx.x, i = b*512 + t;
    int v = (i < NN) ? g_cnt[i] : 0;
    sh[t] = v; __syncthreads();
    for (int o = 1; o < 512; o <<= 1){
        int u = (t >= o) ? sh[t-o] : 0;
        __syncthreads();
        sh[t] += u;
        __syncthreads();
    }
    if (i < NN) g_pscan[i] = sh[t];
    if (t == 511) g_bsum[b] = sh[511];
}
__global__ void csr_scanB(int nb){
    if (threadIdx.x == 0 && blockIdx.x == 0){
        int acc = 0;
        for (int i = 0; i < nb; i++){ g_boff[i] = acc; acc += g_bsum[i]; }
    }
}
__global__ void csr_scanC(){
    int i = blockIdx.x * blockDim.x + threadIdx.x;
    if (i < NN) g_rowptr[i] = g_pscan[i] - g_cnt[i] + g_boff[i >> 9];
}
__global__ void csr_scatter(const void* __restrict__ ei){
    int e = blockIdx.x * blockDim.x + threadIdx.x;
    if (e >= NE) return;
    long long s, d; load_edge(ei, e, s, d);
    int pos = g_rowptr[(int)d] + atomicAdd(&g_cursor[(int)d], 1);
    g_esrc[pos] = (int)s;
}

// ---------------- weight transposes ------------------------------------------
__global__ void transpose4_kernel(const float* __restrict__ W0, const float* __restrict__ W1,
                                  const float* __restrict__ W2, const float* __restrict__ W3){
    int i = blockIdx.x * blockDim.x + threadIdx.x;
    if (i >= 4*128*128) return;
    int j = i >> 14, r = i & 16383, n = r >> 7, k = r & 127;
    const float* W = (j==0)?W0:(j==1)?W1:(j==2)?W2:W3;
    g_wt[(j<<14) + n*128 + k] = W[k*128 + n];
}
__global__ void transpose_kernel(const float* __restrict__ W, int K, int N, float* __restrict__ dst){
    int i = blockIdx.x * blockDim.x + threadIdx.x;
    if (i >= K*N) return;
    int n = i / K, k = i - n*K;
    dst[i] = W[k*N + n];
}

// ---------------- tf32 mma.sync GEMM (register-prefetch pipeline) ------------
struct GemmOuts { float* o[4]; const float* b[4]; };

template<int ACT>
__global__ __launch_bounds__(256) void gemm_mma(
    int M, int K, const float* __restrict__ A, const float* __restrict__ Bt,
    GemmOuts outs, int ldc)
{
    __shared__ float As[16][136];   // [k][m]
    __shared__ float Bs[16][136];   // [k][n]

    const int tid = threadIdx.x, wid = tid >> 5, lane = tid & 31;
    const int gid = lane >> 2, tig = lane & 3;
    const int mbase = blockIdx.y * 128;
    const int xt = blockIdx.x;
    const int wm = (wid & 1) * 64, wn = (wid >> 1) * 32;

    float c[4][4][4];
#pragma unroll
    for (int i = 0; i < 4; i++)
#pragma unroll
        for (int j = 0; j < 4; j++){
            c[i][j][0] = 0.f; c[i][j][1] = 0.f; c[i][j][2] = 0.f; c[i][j][3] = 0.f;
        }

    const float* Bsrc = Bt + (size_t)xt * 128 * K;
    const int mld = tid & 127, hld = tid >> 7;
    const bool arow_ok = (mbase + mld) < M;
    const float* Arow = A + (size_t)(mbase + mld) * K + hld*8;
    const float* Brow = Bsrc + (size_t)mld * K + hld*8;

    // prefetch tile 0
    float4 av0 = arow_ok ? __ldg((const float4*)Arow)       : make_float4(0,0,0,0);
    float4 av1 = arow_ok ? __ldg((const float4*)(Arow + 4)) : make_float4(0,0,0,0);
    float4 bv0 = __ldg((const float4*)Brow);
    float4 bv1 = __ldg((const float4*)(Brow + 4));

    const int kb = hld * 8;
    for (int k0 = 0; k0 < K; k0 += 16){
        As[kb+0][mld] = __uint_as_float(to_tf32(av0.x));
        As[kb+1][mld] = __uint_as_float(to_tf32(av0.y));
        As[kb+2][mld] = __uint_as_float(to_tf32(av0.z));
        As[kb+3][mld] = __uint_as_float(to_tf32(av0.w));
        As[kb+4][mld] = __uint_as_float(to_tf32(av1.x));
        As[kb+5][mld] = __uint_as_float(to_tf32(av1.y));
        As[kb+6][mld] = __uint_as_float(to_tf32(av1.z));
        As[kb+7][mld] = __uint_as_float(to_tf32(av1.w));
        Bs[kb+0][mld] = __uint_as_float(to_tf32(bv0.x));
        Bs[kb+1][mld] = __uint_as_float(to_tf32(bv0.y));
        Bs[kb+2][mld] = __uint_as_float(to_tf32(bv0.z));
        Bs[kb+3][mld] = __uint_as_float(to_tf32(bv0.w));
        Bs[kb+4][mld] = __uint_as_float(to_tf32(bv1.x));
        Bs[kb+5][mld] = __uint_as_float(to_tf32(bv1.y));
        Bs[kb+6][mld] = __uint_as_float(to_tf32(bv1.z));
        Bs[kb+7][mld] = __uint_as_float(to_tf32(bv1.w));
        __syncthreads();

        // prefetch next tile while computing this one
        if (k0 + 16 < K){
            const float* Ap = Arow + k0 + 16;
            const float* Bp = Brow + k0 + 16;
            av0 = arow_ok ? __ldg((const float4*)Ap)       : make_float4(0,0,0,0);
            av1 = arow_ok ? __ldg((const float4*)(Ap + 4)) : make_float4(0,0,0,0);
            bv0 = __ldg((const float4*)Bp);
            bv1 = __ldg((const float4*)(Bp + 4));
        }

#pragma unroll
        for (int kk = 0; kk < 16; kk += 8){
            uint32_t a[4][4], b[4][2];
#pragma unroll
            for (int mf = 0; mf < 4; mf++){
                int m = wm + mf*16 + gid;
                a[mf][0] = __float_as_uint(As[kk+tig  ][m]);
                a[mf][1] = __float_as_uint(As[kk+tig  ][m+8]);
                a[mf][2] = __float_as_uint(As[kk+tig+4][m]);
                a[mf][3] = __float_as_uint(As[kk+tig+4][m+8]);
            }
#pragma unroll
            for (int nf = 0; nf < 4; nf++){
                int n = wn + nf*8 + gid;
                b[nf][0] = __float_as_uint(Bs[kk+tig  ][n]);
                b[nf][1] = __float_as_uint(Bs[kk+tig+4][n]);
            }
#pragma unroll
            for (int mf = 0; mf < 4; mf++)
#pragma unroll
                for (int nf = 0; nf < 4; nf++)
                    mma_tf32(c[mf][nf], a[mf], b[nf]);
        }
        __syncthreads();
    }

    float* obase = outs.o[xt];
    const float* bb = outs.b[xt];
#pragma unroll
    for (int mf = 0; mf < 4; mf++){
#pragma unroll
        for (int half = 0; half < 2; half++){
            int m = mbase + wm + mf*16 + gid + half*8;
            if (m >= M) continue;
            float* op = obase + (size_t)m * ldc;
#pragma unroll
            for (int nf = 0; nf < 4; nf++){
                int n = wn + nf*8 + tig*2;
                float v0 = c[mf][nf][half*2+0] + __ldg(bb + n);
                float v1 = c[mf][nf][half*2+1] + __ldg(bb + n + 1);
                if (ACT == 1){
                    v0 = fmaxf(v0, 0.f); v1 = fmaxf(v1, 0.f);
                } else if (ACT == 2){
                    const float is2 = 0.70710678118654752f;
                    v0 = 0.5f*v0*(1.f + erff(v0*is2));
                    v1 = 0.5f*v1*(1.f + erff(v1*is2));
                }
                *(float2*)(op + n) = make_float2(v0, v1);
            }
        }
    }
}

// ---------------- edge phase: warp per node, online softmax -------------------
__global__ void edge_attn_kernel(){
    int node = (blockIdx.x * blockDim.x + threadIdx.x) >> 5;
    int lane = threadIdx.x & 31;
    if (node >= NN) return;
    size_t base = (size_t)node*HD + lane*4;
    float4 q4 = *(const float4*)(g_q + base);
    const int start = g_rowptr[node], cnt = g_cnt[node];
    float m = -INFINITY, den = 0.f;
    float4 acc = make_float4(0.f, 0.f, 0.f, 0.f);
    for (int i = 0; i < cnt; i++){
        int s = g_esrc[start + i];
        const float* kp = g_k + (size_t)s*HD + lane*4;
        float4 k4 = *(const float4*)kp;
        float d = q4.x*k4.x + q4.y*k4.y + q4.z*k4.z + q4.w*k4.w;
#pragma unroll
        for (int o = 8; o; o >>= 1) d += __shfl_xor_sync(0xffffffffu, d, o);
        float sc = d * 0.125f;                 // / sqrt(64)
        float mn = fmaxf(m, sc);
        float corr = expf(m - mn);             // m=-inf first iter -> 0
        float w = expf(sc - mn);
        float4 v4 = *(const float4*)(g_v + (size_t)s*HD + lane*4);
        den = den*corr + w;
        acc.x = acc.x*corr + w*v4.x;
        acc.y = acc.y*corr + w*v4.y;
        acc.z = acc.z*corr + w*v4.z;
        acc.w = acc.w*corr + w*v4.w;
        m = mn;
    }
    float inv = cnt > 0 ? 1.f/den : 0.f;
    *(float4*)(g_msg + base) = make_float4(acc.x*inv, acc.y*inv, acc.z*inv, acc.w*inv);
}

// ---------------- layernorms -------------------------------------------------
__global__ void ln1_kernel(const float* __restrict__ g, const float* __restrict__ b){
    int node = (blockIdx.x * blockDim.x + threadIdx.x) >> 5;
    int lane = threadIdx.x & 31;
    if (node >= NN) return;
    size_t base = (size_t)node*HD + lane*4;
    float4 zv = *(const float4*)(g_z   + base);
    float4 mv = *(const float4*)(g_msg + base);
    float4 sv = *(const float4*)(g_sk  + base);
    float u[4] = { zv.x + mv.x + sv.x, zv.y + mv.y + sv.y,
                   zv.z + mv.z + sv.z, zv.w + mv.w + sv.w };
    float mu = warp_sum(u[0]+u[1]+u[2]+u[3]) * (1.f/HD);
    float vr = 0.f;
#pragma unroll
    for (int i = 0; i < 4; i++){ float dl = u[i]-mu; vr += dl*dl; }
    vr = warp_sum(vr) * (1.f/HD);
    float rs = rsqrtf(vr + 1e-5f);
    float4 gv = *(const float4*)(g + lane*4);
    float4 bv = *(const float4*)(b + lane*4);
    float4 o;
    o.x = (u[0]-mu)*rs*gv.x + bv.x;
    o.y = (u[1]-mu)*rs*gv.y + bv.y;
    o.z = (u[2]-mu)*rs*gv.z + bv.z;
    o.w = (u[3]-mu)*rs*gv.w + bv.w;
    *(float4*)(g_h + base) = o;
}

__global__ void ln2_kernel(const float* __restrict__ g, const float* __restrict__ b,
                           int betaIdx, float* __restrict__ out){
    int node = (blockIdx.x * blockDim.x + threadIdx.x) >> 5;
    int lane = threadIdx.x & 31;
    if (node >= NN) return;
    size_t base = (size_t)node*HD + lane*4;
    float4 hv = *(const float4*)(g_h + base);
    float4 tv = *(const float4*)(g_t + base);
    float u[4] = { hv.x+tv.x, hv.y+tv.y, hv.z+tv.z, hv.w+tv.w };
    float mu = warp_sum(u[0]+u[1]+u[2]+u[3]) * (1.f/HD);
    float vr = 0.f;
#pragma unroll
    for (int i = 0; i < 4; i++){ float dl = u[i]-mu; vr += dl*dl; }
    vr = warp_sum(vr) * (1.f/HD);
    float rs = rsqrtf(vr + 1e-5f);
    float4 gv = *(const float4*)(g + lane*4);
    float4 bv = *(const float4*)(b + lane*4);
    float zz[4];
#pragma unroll
    for (int i = 0; i < 4; i++){
        float y = (u[i]-mu)*rs;
        y = y * ((i==0)?gv.x:(i==1)?gv.y:(i==2)?gv.z:gv.w)
              + ((i==0)?bv.x:(i==1)?bv.y:(i==2)?bv.z:bv.w);
        zz[i] = fmaxf(y, 0.f);
    }
    *(float4*)(g_z + base) = make_float4(zz[0], zz[1], zz[2], zz[3]);
    float bb = g_betas[betaIdx];
    float4 o = *(float4*)(out + base);
    o.x += bb*zz[0]; o.y += bb*zz[1]; o.z += bb*zz[2]; o.w += bb*zz[3];
    *(float4*)(out + base) = o;
}

__global__ void acc_init_kernel(float* __restrict__ out){
    int i = blockIdx.x * blockDim.x + threadIdx.x;
    if (i < NN*HD) out[i] = g_betas[0] * g_z[i];
}

// ---------------- driver -----------------------------------------------------
extern "C" void kernel_launch(void* const* d_in, const int* in_sizes, int n_in,
                              void* d_out, int out_size)
{
    const float* x    = (const float*)d_in[0];
    const void*  ei   = d_in[1];
    const float* Win  = (const float*)d_in[2];
    const float* b_in = (const float*)d_in[3];
    const float* Wq   = (const float*)d_in[4];
    const float* bq   = (const float*)d_in[5];
    const float* Wk   = (const float*)d_in[6];
    const float* bk   = (const float*)d_in[7];
    const float* Wv   = (const float*)d_in[8];
    const float* bv   = (const float*)d_in[9];
    const float* Wsk  = (const float*)d_in[10];
    const float* bsk  = (const float*)d_in[11];
    const float* W1   = (const float*)d_in[12];
    const float* b1   = (const float*)d_in[13];
    const float* W2   = (const float*)d_in[14];
    const float* b2   = (const float*)d_in[15];
    const float* g1   = (const float*)d_in[16];
    const float* bt1  = (const float*)d_in[17];
    const float* g2   = (const float*)d_in[18];
    const float* bt2  = (const float*)d_in[19];
    const float* beta = (const float*)d_in[20];
    float* out = (float*)d_out;

    float *zP, *qP, *kP, *vP, *skP, *hP, *tP, *ffP, *wtP;
    cudaGetSymbolAddress((void**)&zP,  g_z);
    cudaGetSymbolAddress((void**)&qP,  g_q);
    cudaGetSymbolAddress((void**)&kP,  g_k);
    cudaGetSymbolAddress((void**)&vP,  g_v);
    cudaGetSymbolAddress((void**)&skP, g_sk);
    cudaGetSymbolAddress((void**)&hP,  g_h);
    cudaGetSymbolAddress((void**)&tP,  g_t);
    cudaGetSymbolAddress((void**)&ffP, g_ff);
    cudaGetSymbolAddress((void**)&wtP, g_wt);

    detect_kernel<<<1, 256>>>((const int*)ei);
    betas_kernel<<<1, 32>>>(beta);

    // CSR build (once per launch; depends only on edge_index)
    const int NB_SCAN = (NN + 511) / 512;   // 98
    csr_zero<<<(NN + 255)/256, 256>>>();
    csr_hist<<<(NE + 255)/256, 256>>>(ei);
    csr_scanA<<<NB_SCAN, 512>>>();
    csr_scanB<<<1, 32>>>(NB_SCAN);
    csr_scanC<<<(NN + 255)/256, 256>>>();
    csr_scatter<<<(NE + 255)/256, 256>>>(ei);

    const int MT  = (NN + 127) / 128;        // 391 M-tiles
    const int LNB = (NN + 7) / 8;            // warp/node kernels
    const int IB  = (NN * HD + 255) / 256;

    // z = relu(x @ Win + b_in)
    transpose_kernel<<<(128*128 + 255)/256, 256>>>(Win, HD, HD, wtP);
    {
        GemmOuts o; o.o[0]=zP; o.b[0]=b_in;
        o.o[1]=o.o[2]=o.o[3]=zP; o.b[1]=o.b[2]=o.b[3]=b_in;
        gemm_mma<1><<<dim3(1, MT), 256>>>(NN, HD, x, wtP, o, HD);
    }
    acc_init_kernel<<<IB, 256>>>(out);

    for (int l = 0; l < NL; l++){
        transpose4_kernel<<<(4*128*128 + 255)/256, 256>>>(
            Wq + (size_t)l*HD*HD, Wk + (size_t)l*HD*HD,
            Wv + (size_t)l*HD*HD, Wsk + (size_t)l*HD*HD);
        {
            GemmOuts o;
            o.o[0]=qP;  o.b[0]=bq  + l*HD;
            o.o[1]=kP;  o.b[1]=bk  + l*HD;
            o.o[2]=vP;  o.b[2]=bv  + l*HD;
            o.o[3]=skP; o.b[3]=bsk + l*HD;
            gemm_mma<0><<<dim3(4, MT), 256>>>(NN, HD, zP, wtP, o, HD);
        }

        edge_attn_kernel<<<LNB, 256>>>();
        ln1_kernel<<<LNB, 256>>>(g1 + l*HD, bt1 + l*HD);

        transpose_kernel<<<(128*256 + 255)/256, 256>>>(W1 + (size_t)l*HD*FFD, HD, FFD, wtP);
        {
            GemmOuts o;
            o.o[0]=ffP;       o.b[0]=b1 + l*FFD;
            o.o[1]=ffP + 128; o.b[1]=b1 + l*FFD + 128;
            o.o[2]=o.o[3]=ffP; o.b[2]=o.b[3]=o.b[0];
            gemm_mma<2><<<dim3(2, MT), 256>>>(NN, HD, hP, wtP, o, FFD);
        }
        transpose_kernel<<<(256*128 + 255)/256, 256>>>(W2 + (size_t)l*FFD*HD, FFD, HD, wtP);
        {
            GemmOuts o; o.o[0]=tP; o.b[0]=b2 + l*HD;
            o.o[1]=o.o[2]=o.o[3]=tP; o.b[1]=o.b[2]=o.b[3]=o.b[0];
            gemm_mma<0><<<dim3(1, MT), 256>>>(NN, FFD, ffP, wtP, o, HD);
        }

        ln2_kernel<<<LNB, 256>>>(g2 + l*HD, bt2 + l*HD, l + 1, out);
    }
}

// round 12
// speedup vs baseline: 2.9003x; 1.1245x over previous
#include <cuda_runtime.h>
#include <cmath>
#include <cstdint>

#define NN   50000
#define NE   800000
#define HD   128
#define FFD  256
#define NL   6

// ---------------- scratch (static device globals; no allocs allowed) --------
__device__ float g_z[NN*HD];
__device__ float g_q[NN*HD];
__device__ float g_k[NN*HD];
__device__ float g_v[NN*HD];
__device__ float g_sk[NN*HD];
__device__ float g_msg[NN*HD];
__device__ float g_h[NN*HD];
__device__ float g_t[NN*HD];
__device__ float g_ff[NN*FFD];
__device__ float g_betas[NL+1];
__device__ int   g_mode;              // 1 = edge_index is int64, 0 = int32
// CSR
__device__ int g_cnt[NN];
__device__ int g_rowptr[NN];
__device__ int g_cursor[NN];
__device__ int g_esrc[NE];
__device__ int g_pscan[NN];
__device__ int g_bsum[128];
__device__ int g_boff[128];

// ---------------- helpers ---------------------------------------------------
__device__ __forceinline__ float warp_sum(float v){
#pragma unroll
    for (int o = 16; o; o >>= 1) v += __shfl_xor_sync(0xffffffffu, v, o);
    return v;
}
__device__ __forceinline__ void load_edge(const void* ei, int e, long long& s, long long& d){
    if (g_mode){ const long long* p = (const long long*)ei; s = p[e]; d = p[NE + e]; }
    else       { const int*       p = (const int*)ei;       s = p[e]; d = p[NE + e]; }
}
__device__ __forceinline__ uint32_t to_tf32(float v){
    uint32_t r; asm("cvt.rna.tf32.f32 %0, %1;" : "=r"(r) : "f"(v)); return r;
}
__device__ __forceinline__ void mma_tf32(float* c, const uint32_t* a, const uint32_t* b){
    asm volatile(
        "mma.sync.aligned.m16n8k8.row.col.f32.tf32.tf32.f32 "
        "{%0,%1,%2,%3}, {%4,%5,%6,%7}, {%8,%9}, {%0,%1,%2,%3};"
        : "+f"(c[0]), "+f"(c[1]), "+f"(c[2]), "+f"(c[3])
        : "r"(a[0]), "r"(a[1]), "r"(a[2]), "r"(a[3]), "r"(b[0]), "r"(b[1]));
}

__global__ void detect_kernel(const int* w){
    __shared__ int any;
    if (threadIdx.x == 0) any = 0;
    __syncthreads();
    int loc = 0;
    for (int i = threadIdx.x; i < 2048; i += blockDim.x) loc |= w[2*i + 1];
    if (loc) atomicOr(&any, 1);
    __syncthreads();
    if (threadIdx.x == 0) g_mode = any ? 0 : 1;
}

__global__ void betas_kernel(const float* __restrict__ beta){
    if (threadIdx.x == 0 && blockIdx.x == 0){
        float m = -INFINITY;
        for (int i = 0; i < NL+1; i++) m = fmaxf(m, beta[i]);
        float e[NL+1], s = 0.f;
        for (int i = 0; i < NL+1; i++){ e[i] = expf(beta[i] - m); s += e[i]; }
        for (int i = 0; i < NL+1; i++) g_betas[i] = e[i] / s;
    }
}

// ---------------- CSR build --------------------------------------------------
__global__ void csr_zero(){
    int i = blockIdx.x * blockDim.x + threadIdx.x;
    if (i < NN){ g_cnt[i] = 0; g_cursor[i] = 0; }
}
__global__ void csr_hist(const void* __restrict__ ei){
    int e = blockIdx.x * blockDim.x + threadIdx.x;
    if (e >= NE) return;
    long long s, d; load_edge(ei, e, s, d);
    atomicAdd(&g_cnt[(int)d], 1);
}
__global__ void csr_scanA(){
    __shared__ int sh[512];
    int b = blockIdx.x, t = threadIdx.x, i = b*512 + t;
    int v = (i < NN) ? g_cnt[i] : 0;
    sh[t] = v; __syncthreads();
    for (int o = 1; o < 512; o <<= 1){
        int u = (t >= o) ? sh[t-o] : 0;
        __syncthreads();
        sh[t] += u;
        __syncthreads();
    }
    if (i < NN) g_pscan[i] = sh[t];
    if (t == 511) g_bsum[b] = sh[511];
}
__global__ void csr_scanB(int nb){
    if (threadIdx.x == 0 && blockIdx.x == 0){
        int acc = 0;
        for (int i = 0; i < nb; i++){ g_boff[i] = acc; acc += g_bsum[i]; }
    }
}
__global__ void csr_scanC(){
    int i = blockIdx.x * blockDim.x + threadIdx.x;
    if (i < NN) g_rowptr[i] = g_pscan[i] - g_cnt[i] + g_boff[i >> 9];
}
__global__ void csr_scatter(const void* __restrict__ ei){
    int e = blockIdx.x * blockDim.x + threadIdx.x;
    if (e >= NE) return;
    long long s, d; load_edge(ei, e, s, d);
    int pos = g_rowptr[(int)d] + atomicAdd(&g_cursor[(int)d], 1);
    g_esrc[pos] = (int)s;
}

// ---------------- tf32 mma.sync GEMM -----------------------------------------
// C_tile[xt] = act(A[M,K] @ W[xt][K,128-slice] + bias[xt]).
// W is used IN PLACE (row-major [K][ldw]) — smem B layout is [k][n] anyway.
// Double-buffered smem, one __syncthreads per K-chunk (BK=16).
struct GemmCfg { const float* w[4]; float* o[4]; const float* b[4]; };

template<int ACT>
__global__ __launch_bounds__(256) void gemm_mma(
    int M, int K, int ldw, int ldc,
    const float* __restrict__ A, GemmCfg cfg)
{
    __shared__ float As[2][16][136];   // [buf][k][m]
    __shared__ float Bs[2][16][136];   // [buf][k][n]

    const int tid = threadIdx.x, wid = tid >> 5, lane = tid & 31;
    const int gid = lane >> 2, tig = lane & 3;
    const int mbase = blockIdx.y * 128;
    const int xt = blockIdx.x;
    const int wm = (wid & 1) * 64, wn = (wid >> 1) * 32;

    float c[4][4][4];
#pragma unroll
    for (int i = 0; i < 4; i++)
#pragma unroll
        for (int j = 0; j < 4; j++){
            c[i][j][0] = 0.f; c[i][j][1] = 0.f; c[i][j][2] = 0.f; c[i][j][3] = 0.f;
        }

    // A loader: row mld, k-half hld (8 floats)
    const int mld = tid & 127, hld = tid >> 7;
    const bool arow_ok = (mbase + mld) < M;
    const float* Arow = A + (size_t)(mbase + mld) * K + hld*8;
    const int kb = hld * 8;
    // B loader: k-row kr, 8 columns at nc (coalesced along n)
    const int kr = tid >> 4, nc = (tid & 15) * 8;
    const float* Brow = cfg.w[xt] + (size_t)kr * ldw + nc;

    float4 av0, av1, bw0, bw1;
    // load chunk 0
    av0 = arow_ok ? __ldg((const float4*)Arow)       : make_float4(0,0,0,0);
    av1 = arow_ok ? __ldg((const float4*)(Arow + 4)) : make_float4(0,0,0,0);
    bw0 = __ldg((const float4*)Brow);
    bw1 = __ldg((const float4*)(Brow + 4));
    {
        float* ap = &As[0][kb][mld];
        ap[0*136] = __uint_as_float(to_tf32(av0.x));
        ap[1*136] = __uint_as_float(to_tf32(av0.y));
        ap[2*136] = __uint_as_float(to_tf32(av0.z));
        ap[3*136] = __uint_as_float(to_tf32(av0.w));
        ap[4*136] = __uint_as_float(to_tf32(av1.x));
        ap[5*136] = __uint_as_float(to_tf32(av1.y));
        ap[6*136] = __uint_as_float(to_tf32(av1.z));
        ap[7*136] = __uint_as_float(to_tf32(av1.w));
        float* bp = &Bs[0][kr][nc];
        bp[0] = __uint_as_float(to_tf32(bw0.x));
        bp[1] = __uint_as_float(to_tf32(bw0.y));
        bp[2] = __uint_as_float(to_tf32(bw0.z));
        bp[3] = __uint_as_float(to_tf32(bw0.w));
        bp[4] = __uint_as_float(to_tf32(bw1.x));
        bp[5] = __uint_as_float(to_tf32(bw1.y));
        bp[6] = __uint_as_float(to_tf32(bw1.z));
        bp[7] = __uint_as_float(to_tf32(bw1.w));
    }
    __syncthreads();

    const int nchunk = K >> 4;
    for (int ch = 0; ch < nchunk; ch++){
        const int cur = ch & 1;
        // prefetch chunk ch+1 into registers (overlaps MMA below)
        if (ch + 1 < nchunk){
            const float* Ap = Arow + (ch + 1) * 16;
            const float* Bp = Brow + (size_t)(ch + 1) * 16 * ldw;
            av0 = arow_ok ? __ldg((const float4*)Ap)       : make_float4(0,0,0,0);
            av1 = arow_ok ? __ldg((const float4*)(Ap + 4)) : make_float4(0,0,0,0);
            bw0 = __ldg((const float4*)Bp);
            bw1 = __ldg((const float4*)(Bp + 4));
        }

#pragma unroll
        for (int kk = 0; kk < 16; kk += 8){
            uint32_t a[4][4], b[4][2];
#pragma unroll
            for (int mf = 0; mf < 4; mf++){
                int m = wm + mf*16 + gid;
                a[mf][0] = __float_as_uint(As[cur][kk+tig  ][m]);
                a[mf][1] = __float_as_uint(As[cur][kk+tig  ][m+8]);
                a[mf][2] = __float_as_uint(As[cur][kk+tig+4][m]);
                a[mf][3] = __float_as_uint(As[cur][kk+tig+4][m+8]);
            }
#pragma unroll
            for (int nf = 0; nf < 4; nf++){
                int n = wn + nf*8 + gid;
                b[nf][0] = __float_as_uint(Bs[cur][kk+tig  ][n]);
                b[nf][1] = __float_as_uint(Bs[cur][kk+tig+4][n]);
            }
#pragma unroll
            for (int mf = 0; mf < 4; mf++)
#pragma unroll
                for (int nf = 0; nf < 4; nf++)
                    mma_tf32(c[mf][nf], a[mf], b[nf]);
        }

        if (ch + 1 < nchunk){
            const int nxt = cur ^ 1;
            float* ap = &As[nxt][kb][mld];
            ap[0*136] = __uint_as_float(to_tf32(av0.x));
            ap[1*136] = __uint_as_float(to_tf32(av0.y));
            ap[2*136] = __uint_as_float(to_tf32(av0.z));
            ap[3*136] = __uint_as_float(to_tf32(av0.w));
            ap[4*136] = __uint_as_float(to_tf32(av1.x));
            ap[5*136] = __uint_as_float(to_tf32(av1.y));
            ap[6*136] = __uint_as_float(to_tf32(av1.z));
            ap[7*136] = __uint_as_float(to_tf32(av1.w));
            float* bp = &Bs[nxt][kr][nc];
            bp[0] = __uint_as_float(to_tf32(bw0.x));
            bp[1] = __uint_as_float(to_tf32(bw0.y));
            bp[2] = __uint_as_float(to_tf32(bw0.z));
            bp[3] = __uint_as_float(to_tf32(bw0.w));
            bp[4] = __uint_as_float(to_tf32(bw1.x));
            bp[5] = __uint_as_float(to_tf32(bw1.y));
            bp[6] = __uint_as_float(to_tf32(bw1.z));
            bp[7] = __uint_as_float(to_tf32(bw1.w));
            __syncthreads();
        }
    }

    // epilogue: c0:(m,n) c1:(m,n+1) c2:(m+8,n) c3:(m+8,n+1); n = wn+nf*8+tig*2
    float* obase = cfg.o[xt];
    const float* bb = cfg.b[xt];
#pragma unroll
    for (int mf = 0; mf < 4; mf++){
#pragma unroll
        for (int half = 0; half < 2; half++){
            int m = mbase + wm + mf*16 + gid + half*8;
            if (m >= M) continue;
            float* op = obase + (size_t)m * ldc;
#pragma unroll
            for (int nf = 0; nf < 4; nf++){
                int n = wn + nf*8 + tig*2;
                float v0 = c[mf][nf][half*2+0] + __ldg(bb + n);
                float v1 = c[mf][nf][half*2+1] + __ldg(bb + n + 1);
                if (ACT == 1){
                    v0 = fmaxf(v0, 0.f); v1 = fmaxf(v1, 0.f);
                } else if (ACT == 2){
                    const float is2 = 0.70710678118654752f;
                    v0 = 0.5f*v0*(1.f + erff(v0*is2));
                    v1 = 0.5f*v1*(1.f + erff(v1*is2));
                }
                *(float2*)(op + n) = make_float2(v0, v1);
            }
        }
    }
}

// ---------------- edge phase: warp per node, online softmax -------------------
__global__ void edge_attn_kernel(){
    int node = (blockIdx.x * blockDim.x + threadIdx.x) >> 5;
    int lane = threadIdx.x & 31;
    if (node >= NN) return;
    size_t base = (size_t)node*HD + lane*4;
    float4 q4 = *(const float4*)(g_q + base);
    const int start = g_rowptr[node], cnt = g_cnt[node];
    float m = -INFINITY, den = 0.f;
    float4 acc = make_float4(0.f, 0.f, 0.f, 0.f);
    for (int i = 0; i < cnt; i++){
        int s = g_esrc[start + i];
        float4 k4 = *(const float4*)(g_k + (size_t)s*HD + lane*4);
        float d = q4.x*k4.x + q4.y*k4.y + q4.z*k4.z + q4.w*k4.w;
#pragma unroll
        for (int o = 8; o; o >>= 1) d += __shfl_xor_sync(0xffffffffu, d, o);
        float sc = d * 0.125f;                 // / sqrt(64)
        float mn = fmaxf(m, sc);
        float corr = expf(m - mn);             // m=-inf first iter -> 0
        float w = expf(sc - mn);
        float4 v4 = *(const float4*)(g_v + (size_t)s*HD + lane*4);
        den = den*corr + w;
        acc.x = acc.x*corr + w*v4.x;
        acc.y = acc.y*corr + w*v4.y;
        acc.z = acc.z*corr + w*v4.z;
        acc.w = acc.w*corr + w*v4.w;
        m = mn;
    }
    float inv = cnt > 0 ? 1.f/den : 0.f;
    *(float4*)(g_msg + base) = make_float4(acc.x*inv, acc.y*inv, acc.z*inv, acc.w*inv);
}

// ---------------- layernorms -------------------------------------------------
__global__ void ln1_kernel(const float* __restrict__ g, const float* __restrict__ b){
    int node = (blockIdx.x * blockDim.x + threadIdx.x) >> 5;
    int lane = threadIdx.x & 31;
    if (node >= NN) return;
    size_t base = (size_t)node*HD + lane*4;
    float4 zv = *(const float4*)(g_z   + base);
    float4 mv = *(const float4*)(g_msg + base);
    float4 sv = *(const float4*)(g_sk  + base);
    float u[4] = { zv.x + mv.x + sv.x, zv.y + mv.y + sv.y,
                   zv.z + mv.z + sv.z, zv.w + mv.w + sv.w };
    float mu = warp_sum(u[0]+u[1]+u[2]+u[3]) * (1.f/HD);
    float vr = 0.f;
#pragma unroll
    for (int i = 0; i < 4; i++){ float dl = u[i]-mu; vr += dl*dl; }
    vr = warp_sum(vr) * (1.f/HD);
    float rs = rsqrtf(vr + 1e-5f);
    float4 gv = *(const float4*)(g + lane*4);
    float4 bv = *(const float4*)(b + lane*4);
    float4 o;
    o.x = (u[0]-mu)*rs*gv.x + bv.x;
    o.y = (u[1]-mu)*rs*gv.y + bv.y;
    o.z = (u[2]-mu)*rs*gv.z + bv.z;
    o.w = (u[3]-mu)*rs*gv.w + bv.w;
    *(float4*)(g_h + base) = o;
}

__global__ void ln2_kernel(const float* __restrict__ g, const float* __restrict__ b,
                           int betaIdx, float* __restrict__ out){
    int node = (blockIdx.x * blockDim.x + threadIdx.x) >> 5;
    int lane = threadIdx.x & 31;
    if (node >= NN) return;
    size_t base = (size_t)node*HD + lane*4;
    float4 hv = *(const float4*)(g_h + base);
    float4 tv = *(const float4*)(g_t + base);
    float u[4] = { hv.x+tv.x, hv.y+tv.y, hv.z+tv.z, hv.w+tv.w };
    float mu = warp_sum(u[0]+u[1]+u[2]+u[3]) * (1.f/HD);
    float vr = 0.f;
#pragma unroll
    for (int i = 0; i < 4; i++){ float dl = u[i]-mu; vr += dl*dl; }
    vr = warp_sum(vr) * (1.f/HD);
    float rs = rsqrtf(vr + 1e-5f);
    float4 gv = *(const float4*)(g + lane*4);
    float4 bv = *(const float4*)(b + lane*4);
    float zz[4];
#pragma unroll
    for (int i = 0; i < 4; i++){
        float y = (u[i]-mu)*rs;
        y = y * ((i==0)?gv.x:(i==1)?gv.y:(i==2)?gv.z:gv.w)
              + ((i==0)?bv.x:(i==1)?bv.y:(i==2)?bv.z:bv.w);
        zz[i] = fmaxf(y, 0.f);
    }
    *(float4*)(g_z + base) = make_float4(zz[0], zz[1], zz[2], zz[3]);
    float bb = g_betas[betaIdx];
    float4 o = *(float4*)(out + base);
    o.x += bb*zz[0]; o.y += bb*zz[1]; o.z += bb*zz[2]; o.w += bb*zz[3];
    *(float4*)(out + base) = o;
}

__global__ void acc_init_kernel(float* __restrict__ out){
    int i = blockIdx.x * blockDim.x + threadIdx.x;
    if (i < NN*HD) out[i] = g_betas[0] * g_z[i];
}

// ---------------- driver -----------------------------------------------------
extern "C" void kernel_launch(void* const* d_in, const int* in_sizes, int n_in,
                              void* d_out, int out_size)
{
    const float* x    = (const float*)d_in[0];
    const void*  ei   = d_in[1];
    const float* Win  = (const float*)d_in[2];
    const float* b_in = (const float*)d_in[3];
    const float* Wq   = (const float*)d_in[4];
    const float* bq   = (const float*)d_in[5];
    const float* Wk   = (const float*)d_in[6];
    const float* bk   = (const float*)d_in[7];
    const float* Wv   = (const float*)d_in[8];
    const float* bv   = (const float*)d_in[9];
    const float* Wsk  = (const float*)d_in[10];
    const float* bsk  = (const float*)d_in[11];
    const float* W1   = (const float*)d_in[12];
    const float* b1   = (const float*)d_in[13];
    const float* W2   = (const float*)d_in[14];
    const float* b2   = (const float*)d_in[15];
    const float* g1   = (const float*)d_in[16];
    const float* bt1  = (const float*)d_in[17];
    const float* g2   = (const float*)d_in[18];
    const float* bt2  = (const float*)d_in[19];
    const float* beta = (const float*)d_in[20];
    float* out = (float*)d_out;

    float *zP, *qP, *kP, *vP, *skP, *hP, *tP, *ffP;
    cudaGetSymbolAddress((void**)&zP,  g_z);
    cudaGetSymbolAddress((void**)&qP,  g_q);
    cudaGetSymbolAddress((void**)&kP,  g_k);
    cudaGetSymbolAddress((void**)&vP,  g_v);
    cudaGetSymbolAddress((void**)&skP, g_sk);
    cudaGetSymbolAddress((void**)&hP,  g_h);
    cudaGetSymbolAddress((void**)&tP,  g_t);
    cudaGetSymbolAddress((void**)&ffP, g_ff);

    detect_kernel<<<1, 256>>>((const int*)ei);
    betas_kernel<<<1, 32>>>(beta);

    // CSR build (once per launch; depends only on edge_index)
    const int NB_SCAN = (NN + 511) / 512;   // 98
    csr_zero<<<(NN + 255)/256, 256>>>();
    csr_hist<<<(NE + 255)/256, 256>>>(ei);
    csr_scanA<<<NB_SCAN, 512>>>();
    csr_scanB<<<1, 32>>>(NB_SCAN);
    csr_scanC<<<(NN + 255)/256, 256>>>();
    csr_scatter<<<(NE + 255)/256, 256>>>(ei);

    const int MT  = (NN + 127) / 128;        // 391 M-tiles
    const int LNB = (NN + 7) / 8;            // warp/node kernels
    const int IB  = (NN * HD + 255) / 256;

    // z = relu(x @ Win + b_in)
    {
        GemmCfg c;
        c.w[0]=c.w[1]=c.w[2]=c.w[3]=Win;
        c.o[0]=c.o[1]=c.o[2]=c.o[3]=zP;
        c.b[0]=c.b[1]=c.b[2]=c.b[3]=b_in;
        gemm_mma<1><<<dim3(1, MT), 256>>>(NN, HD, HD, HD, x, c);
    }
    acc_init_kernel<<<IB, 256>>>(out);

    for (int l = 0; l < NL; l++){
        {   // fused q/k/v/sk projections (weights used in place)
            GemmCfg c;
            c.w[0]=Wq  + (size_t)l*HD*HD; c.o[0]=qP;  c.b[0]=bq  + l*HD;
            c.w[1]=Wk  + (size_t)l*HD*HD; c.o[1]=kP;  c.b[1]=bk  + l*HD;
            c.w[2]=Wv  + (size_t)l*HD*HD; c.o[2]=vP;  c.b[2]=bv  + l*HD;
            c.w[3]=Wsk + (size_t)l*HD*HD; c.o[3]=skP; c.b[3]=bsk + l*HD;
            gemm_mma<0><<<dim3(4, MT), 256>>>(NN, HD, HD, HD, zP, c);
        }

        edge_attn_kernel<<<LNB, 256>>>();
        ln1_kernel<<<LNB, 256>>>(g1 + l*HD, bt1 + l*HD);

        {   // ff = gelu(h @ W1 + b1): two 128-col tiles of W1 [128,256]
            const float* W1l = W1 + (size_t)l*HD*FFD;
            GemmCfg c;
            c.w[0]=W1l;       c.o[0]=ffP;       c.b[0]=b1 + l*FFD;
            c.w[1]=W1l + 128; c.o[1]=ffP + 128; c.b[1]=b1 + l*FFD + 128;
            c.w[2]=c.w[0];    c.o[2]=c.o[0];    c.b[2]=c.b[0];
            c.w[3]=c.w[0];    c.o[3]=c.o[0];    c.b[3]=c.b[0];
            gemm_mma<2><<<dim3(2, MT), 256>>>(NN, HD, FFD, FFD, hP, c);
        }
        {   // t = ff @ W2 + b2  (K=256)
            GemmCfg c;
            c.w[0]=W2 + (size_t)l*FFD*HD; c.o[0]=tP; c.b[0]=b2 + l*HD;
            c.w[1]=c.w[0]; c.o[1]=c.o[0]; c.b[1]=c.b[0];
            c.w[2]=c.w[0]; c.o[2]=c.o[0]; c.b[2]=c.b[0];
            c.w[3]=c.w[0]; c.o[3]=c.o[0]; c.b[3]=c.b[0];
            gemm_mma<0><<<dim3(1, MT), 256>>>(NN, FFD, HD, HD, ffP, c);
        }

        ln2_kernel<<<LNB, 256>>>(g2 + l*HD, bt2 + l*HD, l + 1, out);
    }
}

// round 15
// speedup vs baseline: 2.9904x; 1.0311x over previous
#include <cuda_runtime.h>
#include <cmath>
#include <cstdint>

#define NN   50000
#define NE   800000
#define HD   128
#define FFD  256
#define NL   6

// ---------------- scratch (static device globals; no allocs allowed) --------
__device__ float g_z[NN*HD];
__device__ float g_q[NN*HD];
__device__ float g_k[NN*HD];
__device__ float g_v[NN*HD];
__device__ float g_sk[NN*HD];
__device__ float g_h[NN*HD];
__device__ float g_t[NN*HD];
__device__ float g_ff[NN*FFD];
__device__ float g_betas[NL+1];
__device__ int   g_mode;              // 1 = edge_index is int64, 0 = int32
// CSR
__device__ int g_cnt[NN];
__device__ int g_rowptr[NN];
__device__ int g_cursor[NN];
__device__ int g_esrc[NE];
__device__ int g_pscan[NN];
__device__ int g_bsum[128];
__device__ int g_boff[128];

// ---------------- helpers ---------------------------------------------------
__device__ __forceinline__ float warp_sum(float v){
#pragma unroll
    for (int o = 16; o; o >>= 1) v += __shfl_xor_sync(0xffffffffu, v, o);
    return v;
}
__device__ __forceinline__ void load_edge(const void* ei, int e, long long& s, long long& d){
    if (g_mode){ const long long* p = (const long long*)ei; s = p[e]; d = p[NE + e]; }
    else       { const int*       p = (const int*)ei;       s = p[e]; d = p[NE + e]; }
}
__device__ __forceinline__ float tf32f(float v){
    uint32_t r; asm("cvt.rna.tf32.f32 %0, %1;" : "=r"(r) : "f"(v));
    return __uint_as_float(r);
}
__device__ __forceinline__ void mma_tf32(float* c, const uint32_t* a, const uint32_t* b){
    asm volatile(
        "mma.sync.aligned.m16n8k8.row.col.f32.tf32.tf32.f32 "
        "{%0,%1,%2,%3}, {%4,%5,%6,%7}, {%8,%9}, {%0,%1,%2,%3};"
        : "+f"(c[0]), "+f"(c[1]), "+f"(c[2]), "+f"(c[3])
        : "r"(a[0]), "r"(a[1]), "r"(a[2]), "r"(a[3]), "r"(b[0]), "r"(b[1]));
}

__global__ void detect_kernel(const int* w){
    __shared__ int any;
    if (threadIdx.x == 0) any = 0;
    __syncthreads();
    int loc = 0;
    for (int i = threadIdx.x; i < 2048; i += blockDim.x) loc |= w[2*i + 1];
    if (loc) atomicOr(&any, 1);
    __syncthreads();
    if (threadIdx.x == 0) g_mode = any ? 0 : 1;
}

__global__ void betas_kernel(const float* __restrict__ beta){
    if (threadIdx.x == 0 && blockIdx.x == 0){
        float m = -INFINITY;
        for (int i = 0; i < NL+1; i++) m = fmaxf(m, beta[i]);
        float e[NL+1], s = 0.f;
        for (int i = 0; i < NL+1; i++){ e[i] = expf(beta[i] - m); s += e[i]; }
        for (int i = 0; i < NL+1; i++) g_betas[i] = e[i] / s;
    }
}

// ---------------- CSR build --------------------------------------------------
__global__ void csr_zero(){
    int i = blockIdx.x * blockDim.x + threadIdx.x;
    if (i < NN){ g_cnt[i] = 0; g_cursor[i] = 0; }
}
__global__ void csr_hist(const void* __restrict__ ei){
    int e = blockIdx.x * blockDim.x + threadIdx.x;
    if (e >= NE) return;
    long long s, d; load_edge(ei, e, s, d);
    atomicAdd(&g_cnt[(int)d], 1);
}
__global__ void csr_scanA(){
    __shared__ int sh[512];
    int b = blockIdx.x, t = threadIdx.x, i = b*512 + t;
    int v = (i < NN) ? g_cnt[i] : 0;
    sh[t] = v; __syncthreads();
    for (int o = 1; o < 512; o <<= 1){
        int u = (t >= o) ? sh[t-o] : 0;
        __syncthreads();
        sh[t] += u;
        __syncthreads();
    }
    if (i < NN) g_pscan[i] = sh[t];
    if (t == 511) g_bsum[b] = sh[511];
}
__global__ void csr_scanB(int nb){
    if (threadIdx.x == 0 && blockIdx.x == 0){
        int acc = 0;
        for (int i = 0; i < nb; i++){ g_boff[i] = acc; acc += g_bsum[i]; }
    }
}
__global__ void csr_scanC(){
    int i = blockIdx.x * blockDim.x + threadIdx.x;
    if (i < NN) g_rowptr[i] = g_pscan[i] - g_cnt[i] + g_boff[i >> 9];
}
__global__ void csr_scatter(const void* __restrict__ ei){
    int e = blockIdx.x * blockDim.x + threadIdx.x;
    if (e >= NE) return;
    long long s, d; load_edge(ei, e, s, d);
    int pos = g_rowptr[(int)d] + atomicAdd(&g_cursor[(int)d], 1);
    g_esrc[pos] = (int)s;
}

// ---------------- tf32 mma.sync GEMM (vectorized fragment smem) --------------
// C_tile[xt] = act(A[M,K] @ W[xt][K,128-slice] + bias[xt]).
// As4: each float4 = one A-fragment {(m,k),(m+8,k),(m,k+4),(m+8,k+4)}.
// Bs2: each float2 = one B-fragment pair {(k,n),(k+4,n)}.
struct GemmCfg { const float* w[4]; float* o[4]; const float* b[4]; };

template<int ACT>
__global__ __launch_bounds__(256, 2) void gemm_mma(
    int M, int K, int ldw, int ldc,
    const float* __restrict__ A, GemmCfg cfg)
{
    __shared__ float4 As4[2][8][66];    // [buf][kk2*4+tig][pair(64)+pad]
    __shared__ float2 Bs2[2][8][132];   // [buf][kk2*4+tig][n(128)+pad]

    const int tid = threadIdx.x, wid = tid >> 5, lane = tid & 31;
    const int gid = lane >> 2, tig = lane & 3;
    const int mbase = blockIdx.y * 128;
    const int xt = blockIdx.x;
    const int wmg = (wid & 1) * 4;      // m>>4 base of warp tile
    const int wn  = (wid >> 1) * 32;

    float c[4][4][4];
#pragma unroll
    for (int i = 0; i < 4; i++)
#pragma unroll
        for (int j = 0; j < 4; j++){
            c[i][j][0] = 0.f; c[i][j][1] = 0.f; c[i][j][2] = 0.f; c[i][j][3] = 0.f;
        }

    // A loader: row mld, k-half hld (8 floats); hld == kk2 of this chunk part
    const int mld = tid & 127, hld = tid >> 7;
    const bool arow_ok = (mbase + mld) < M;
    const float* Arow = A + (size_t)(mbase + mld) * K + hld*8;
    const int apair = ((mld >> 4) << 3) + (mld & 7);
    const int ab3 = (mld >> 3) & 1;
    // B loader: k-row kr (0..15), n stripe t16 + 16j
    const int t16 = tid & 15, kr = tid >> 4;
    const float* Brow = cfg.w[xt] + (size_t)kr * ldw + t16;
    const int bplane = ((kr >> 3) << 2) + (kr & 3);
    const int bkh = (kr >> 2) & 1;

    float4 av0, av1;
    float bw[8];

    av0 = arow_ok ? __ldg((const float4*)Arow)       : make_float4(0,0,0,0);
    av1 = arow_ok ? __ldg((const float4*)(Arow + 4)) : make_float4(0,0,0,0);
#pragma unroll
    for (int j = 0; j < 8; j++) bw[j] = __ldg(Brow + j*16);

    {
        float* p0 = (float*)&As4[0][hld*4+0][apair];
        float* p1 = (float*)&As4[0][hld*4+1][apair];
        float* p2 = (float*)&As4[0][hld*4+2][apair];
        float* p3 = (float*)&As4[0][hld*4+3][apair];
        p0[ab3] = tf32f(av0.x); p0[2+ab3] = tf32f(av1.x);
        p1[ab3] = tf32f(av0.y); p1[2+ab3] = tf32f(av1.y);
        p2[ab3] = tf32f(av0.z); p2[2+ab3] = tf32f(av1.z);
        p3[ab3] = tf32f(av0.w); p3[2+ab3] = tf32f(av1.w);
        float* q = ((float*)&Bs2[0][bplane][0]) + bkh;
#pragma unroll
        for (int j = 0; j < 8; j++) q[(t16 + 16*j)*2] = tf32f(bw[j]);
    }
    __syncthreads();

    const int nchunk = K >> 4;
    for (int ch = 0; ch < nchunk; ch++){
        const int cur = ch & 1;
        if (ch + 1 < nchunk){
            const float* Ap = Arow + (ch + 1) * 16;
            const float* Bp = Brow + (size_t)(ch + 1) * 16 * ldw;
            av0 = arow_ok ? __ldg((const float4*)Ap)       : make_float4(0,0,0,0);
            av1 = arow_ok ? __ldg((const float4*)(Ap + 4)) : make_float4(0,0,0,0);
#pragma unroll
            for (int j = 0; j < 8; j++) bw[j] = __ldg(Bp + j*16);
        }

#pragma unroll
        for (int kk2 = 0; kk2 < 2; kk2++){
            const int pl = kk2*4 + tig;
            float4 a4[4]; float2 b2[4];
#pragma unroll
            for (int mf = 0; mf < 4; mf++)
                a4[mf] = As4[cur][pl][(wmg + mf)*8 + gid];
#pragma unroll
            for (int nf = 0; nf < 4; nf++)
                b2[nf] = Bs2[cur][pl][wn + nf*8 + gid];
#pragma unroll
            for (int mf = 0; mf < 4; mf++)
#pragma unroll
                for (int nf = 0; nf < 4; nf++)
                    mma_tf32(c[mf][nf], (const uint32_t*)&a4[mf], (const uint32_t*)&b2[nf]);
        }

        if (ch + 1 < nchunk){
            const int nxt = cur ^ 1;
            float* p0 = (float*)&As4[nxt][hld*4+0][apair];
            float* p1 = (float*)&As4[nxt][hld*4+1][apair];
            float* p2 = (float*)&As4[nxt][hld*4+2][apair];
            float* p3 = (float*)&As4[nxt][hld*4+3][apair];
            p0[ab3] = tf32f(av0.x); p0[2+ab3] = tf32f(av1.x);
            p1[ab3] = tf32f(av0.y); p1[2+ab3] = tf32f(av1.y);
            p2[ab3] = tf32f(av0.z); p2[2+ab3] = tf32f(av1.z);
            p3[ab3] = tf32f(av0.w); p3[2+ab3] = tf32f(av1.w);
            float* q = ((float*)&Bs2[nxt][bplane][0]) + bkh;
#pragma unroll
            for (int j = 0; j < 8; j++) q[(t16 + 16*j)*2] = tf32f(bw[j]);
            __syncthreads();
        }
    }

    // epilogue: c0:(m,n) c1:(m,n+1) c2:(m+8,n) c3:(m+8,n+1); n = wn+nf*8+tig*2
    float* obase = cfg.o[xt];
    const float* bb = cfg.b[xt];
    const int wm = wmg * 16;
#pragma unroll
    for (int mf = 0; mf < 4; mf++){
#pragma unroll
        for (int half = 0; half < 2; half++){
            int m = mbase + wm + mf*16 + gid + half*8;
            if (m >= M) continue;
            float* op = obase + (size_t)m * ldc;
#pragma unroll
            for (int nf = 0; nf < 4; nf++){
                int n = wn + nf*8 + tig*2;
                float v0 = c[mf][nf][half*2+0] + __ldg(bb + n);
                float v1 = c[mf][nf][half*2+1] + __ldg(bb + n + 1);
                if (ACT == 1){
                    v0 = fmaxf(v0, 0.f); v1 = fmaxf(v1, 0.f);
                } else if (ACT == 2){
                    const float is2 = 0.70710678118654752f;
                    v0 = 0.5f*v0*(1.f + erff(v0*is2));
                    v1 = 0.5f*v1*(1.f + erff(v1*is2));
                }
                *(float2*)(op + n) = make_float2(v0, v1);
            }
        }
    }
}

// ---------------- edge phase + ln1 fused: warp per node ----------------------
__global__ void edge_attn_ln1_kernel(const float* __restrict__ g, const float* __restrict__ b){
    int node = (blockIdx.x * blockDim.x + threadIdx.x) >> 5;
    int lane = threadIdx.x & 31;
    if (node >= NN) return;
    size_t base = (size_t)node*HD + lane*4;
    float4 q4 = *(const float4*)(g_q + base);
    const int start = g_rowptr[node], cnt = g_cnt[node];
    float m = -INFINITY, den = 0.f;
    float4 acc = make_float4(0.f, 0.f, 0.f, 0.f);
    for (int i = 0; i < cnt; i++){
        int s = g_esrc[start + i];
        float4 k4 = *(const float4*)(g_k + (size_t)s*HD + lane*4);
        float d = q4.x*k4.x + q4.y*k4.y + q4.z*k4.z + q4.w*k4.w;
#pragma unroll
        for (int o = 8; o; o >>= 1) d += __shfl_xor_sync(0xffffffffu, d, o);
        float sc = d * 0.125f;                 // / sqrt(64)
        float mn = fmaxf(m, sc);
        float corr = expf(m - mn);             // m=-inf first iter -> 0
        float w = expf(sc - mn);
        float4 v4 = *(const float4*)(g_v + (size_t)s*HD + lane*4);
        den = den*corr + w;
        acc.x = acc.x*corr + w*v4.x;
        acc.y = acc.y*corr + w*v4.y;
        acc.z = acc.z*corr + w*v4.z;
        acc.w = acc.w*corr + w*v4.w;
        m = mn;
    }
    float inv = cnt > 0 ? 1.f/den : 0.f;
    // fused ln1: h = LN(z + msg + sk) * g + b
    float4 zv = *(const float4*)(g_z  + base);
    float4 sv = *(const float4*)(g_sk + base);
    float u[4] = { zv.x + acc.x*inv + sv.x, zv.y + acc.y*inv + sv.y,
                   zv.z + acc.z*inv + sv.z, zv.w + acc.w*inv + sv.w };
    float mu = warp_sum(u[0]+u[1]+u[2]+u[3]) * (1.f/HD);
    float vr = 0.f;
#pragma unroll
    for (int i = 0; i < 4; i++){ float dl = u[i]-mu; vr += dl*dl; }
    vr = warp_sum(vr) * (1.f/HD);
    float rs = rsqrtf(vr + 1e-5f);
    float4 gv = *(const float4*)(g + lane*4);
    float4 bv = *(const float4*)(b + lane*4);
    float4 o;
    o.x = (u[0]-mu)*rs*gv.x + bv.x;
    o.y = (u[1]-mu)*rs*gv.y + bv.y;
    o.z = (u[2]-mu)*rs*gv.z + bv.z;
    o.w = (u[3]-mu)*rs*gv.w + bv.w;
    *(float4*)(g_h + base) = o;
}

// ---------------- ln2 --------------------------------------------------------
__global__ void ln2_kernel(const float* __restrict__ g, const float* __restrict__ b,
                           int betaIdx, float* __restrict__ out){
    int node = (blockIdx.x * blockDim.x + threadIdx.x) >> 5;
    int lane = threadIdx.x & 31;
    if (node >= NN) return;
    size_t base = (size_t)node*HD + lane*4;
    float4 hv = *(const float4*)(g_h + base);
    float4 tv = *(const float4*)(g_t + base);
    float u[4] = { hv.x+tv.x, hv.y+tv.y, hv.z+tv.z, hv.w+tv.w };
    float mu = warp_sum(u[0]+u[1]+u[2]+u[3]) * (1.f/HD);
    float vr = 0.f;
#pragma unroll
    for (int i = 0; i < 4; i++){ float dl = u[i]-mu; vr += dl*dl; }
    vr = warp_sum(vr) * (1.f/HD);
    float rs = rsqrtf(vr + 1e-5f);
    float4 gv = *(const float4*)(g + lane*4);
    float4 bv = *(const float4*)(b + lane*4);
    float zz[4];
#pragma unroll
    for (int i = 0; i < 4; i++){
        float y = (u[i]-mu)*rs;
        y = y * ((i==0)?gv.x:(i==1)?gv.y:(i==2)?gv.z:gv.w)
              + ((i==0)?bv.x:(i==1)?bv.y:(i==2)?bv.z:bv.w);
        zz[i] = fmaxf(y, 0.f);
    }
    *(float4*)(g_z + base) = make_float4(zz[0], zz[1], zz[2], zz[3]);
    float bb = g_betas[betaIdx];
    float4 o = *(float4*)(out + base);
    o.x += bb*zz[0]; o.y += bb*zz[1]; o.z += bb*zz[2]; o.w += bb*zz[3];
    *(float4*)(out + base) = o;
}

__global__ void acc_init_kernel(float* __restrict__ out){
    int i = blockIdx.x * blockDim.x + threadIdx.x;
    if (i < NN*HD) out[i] = g_betas[0] * g_z[i];
}

// ---------------- driver -----------------------------------------------------
extern "C" void kernel_launch(void* const* d_in, const int* in_sizes, int n_in,
                              void* d_out, int out_size)
{
    const float* x    = (const float*)d_in[0];
    const void*  ei   = d_in[1];
    const float* Win  = (const float*)d_in[2];
    const float* b_in = (const float*)d_in[3];
    const float* Wq   = (const float*)d_in[4];
    const float* bq   = (const float*)d_in[5];
    const float* Wk   = (const float*)d_in[6];
    const float* bk   = (const float*)d_in[7];
    const float* Wv   = (const float*)d_in[8];
    const float* bv   = (const float*)d_in[9];
    const float* Wsk  = (const float*)d_in[10];
    const float* bsk  = (const float*)d_in[11];
    const float* W1   = (const float*)d_in[12];
    const float* b1   = (const float*)d_in[13];
    const float* W2   = (const float*)d_in[14];
    const float* b2   = (const float*)d_in[15];
    const float* g1   = (const float*)d_in[16];
    const float* bt1  = (const float*)d_in[17];
    const float* g2   = (const float*)d_in[18];
    const float* bt2  = (const float*)d_in[19];
    const float* beta = (const float*)d_in[20];
    float* out = (float*)d_out;

    float *zP, *qP, *kP, *vP, *skP, *hP, *tP, *ffP;
    cudaGetSymbolAddress((void**)&zP,  g_z);
    cudaGetSymbolAddress((void**)&qP,  g_q);
    cudaGetSymbolAddress((void**)&kP,  g_k);
    cudaGetSymbolAddress((void**)&vP,  g_v);
    cudaGetSymbolAddress((void**)&skP, g_sk);
    cudaGetSymbolAddress((void**)&hP,  g_h);
    cudaGetSymbolAddress((void**)&tP,  g_t);
    cudaGetSymbolAddress((void**)&ffP, g_ff);

    detect_kernel<<<1, 256>>>((const int*)ei);
    betas_kernel<<<1, 32>>>(beta);

    // CSR build (once per launch; depends only on edge_index)
    const int NB_SCAN = (NN + 511) / 512;   // 98
    csr_zero<<<(NN + 255)/256, 256>>>();
    csr_hist<<<(NE + 255)/256, 256>>>(ei);
    csr_scanA<<<NB_SCAN, 512>>>();
    csr_scanB<<<1, 32>>>(NB_SCAN);
    csr_scanC<<<(NN + 255)/256, 256>>>();
    csr_scatter<<<(NE + 255)/256, 256>>>(ei);

    const int MT  = (NN + 127) / 128;        // 391 M-tiles
    const int LNB = (NN + 7) / 8;            // warp/node kernels
    const int IB  = (NN * HD + 255) / 256;

    // z = relu(x @ Win + b_in)
    {
        GemmCfg c;
        c.w[0]=c.w[1]=c.w[2]=c.w[3]=Win;
        c.o[0]=c.o[1]=c.o[2]=c.o[3]=zP;
        c.b[0]=c.b[1]=c.b[2]=c.b[3]=b_in;
        gemm_mma<1><<<dim3(1, MT), 256>>>(NN, HD, HD, HD, x, c);
    }
    acc_init_kernel<<<IB, 256>>>(out);

    for (int l = 0; l < NL; l++){
        {   // fused q/k/v/sk projections (weights used in place)
            GemmCfg c;
            c.w[0]=Wq  + (size_t)l*HD*HD; c.o[0]=qP;  c.b[0]=bq  + l*HD;
            c.w[1]=Wk  + (size_t)l*HD*HD; c.o[1]=kP;  c.b[1]=bk  + l*HD;
            c.w[2]=Wv  + (size_t)l*HD*HD; c.o[2]=vP;  c.b[2]=bv  + l*HD;
            c.w[3]=Wsk + (size_t)l*HD*HD; c.o[3]=skP; c.b[3]=bsk + l*HD;
            gemm_mma<0><<<dim3(4, MT), 256>>>(NN, HD, HD, HD, zP, c);
        }

        edge_attn_ln1_kernel<<<LNB, 256>>>(g1 + l*HD, bt1 + l*HD);

        {   // ff = gelu(h @ W1 + b1): two 128-col tiles of W1 [128,256]
            const float* W1l = W1 + (size_t)l*HD*FFD;
            GemmCfg c;
            c.w[0]=W1l;       c.o[0]=ffP;       c.b[0]=b1 + l*FFD;
            c.w[1]=W1l + 128; c.o[1]=ffP + 128; c.b[1]=b1 + l*FFD + 128;
            c.w[2]=c.w[0];    c.o[2]=c.o[0];    c.b[2]=c.b[0];
            c.w[3]=c.w[0];    c.o[3]=c.o[0];    c.b[3]=c.b[0];
            gemm_mma<2><<<dim3(2, MT), 256>>>(NN, HD, FFD, FFD, hP, c);
        }
        {   // t = ff @ W2 + b2  (K=256)
            GemmCfg c;
            c.w[0]=W2 + (size_t)l*FFD*HD; c.o[0]=tP; c.b[0]=b2 + l*HD;
            c.w[1]=c.w[0]; c.o[1]=c.o[0]; c.b[1]=c.b[0];
            c.w[2]=c.w[0]; c.o[2]=c.o[0]; c.b[2]=c.b[0];
            c.w[3]=c.w[0]; c.o[3]=c.o[0]; c.b[3]=c.b[0];
            gemm_mma<0><<<dim3(1, MT), 256>>>(NN, FFD, HD, HD, ffP, c);
        }

        ln2_kernel<<<LNB, 256>>>(g2 + l*HD, bt2 + l*HD, l + 1, out);
    }
}